// round 2
// baseline (speedup 1.0000x reference)
#include <cuda_runtime.h>
#include <cuda_bf16.h>

// ---------------- problem constants ----------------
#define NBAGS 512
#define MSENT 8
#define TLEN  64
#define IND   360
#define HID   230
#define OUTD  53
#define NDOCS 32
#define NENT  8

#define BATCH (NBAGS*MSENT)   // 4096
#define G3    (3*HID)         // 690
#define HH2   (2*HID)         // 460
#define MTOK  (BATCH*TLEN)    // 262144
#define NPART 8               // ceil(460/64)

// ---------------- scratch (device globals; no allocation allowed) ----------------
__device__ float g_xg_f[(size_t)BATCH*TLEN*G3];     // (B,T,3H) input-proj forward
__device__ float g_xg_r[(size_t)BATCH*TLEN*G3];     // (B,T,3H) input-proj reverse
__device__ float g_out [(size_t)TLEN*BATCH*HH2];    // (T,B,2H) concat hidden states
__device__ float g_hg  [(size_t)2*BATCH*G3];        // per-step hg scratch (both dirs)
__device__ float g_partial [(size_t)MTOK*NPART];    // word attn score partials
__device__ float g_scores  [(size_t)BATCH*TLEN];    // word scores/alpha, (B,T)
__device__ float g_wordvec [(size_t)BATCH*HH2];     // (B,2H)
__device__ float g_partial2[(size_t)BATCH*NPART];   // sent attn partials
__device__ float g_scores2 [BATCH];                 // sent scores/beta
__device__ float g_sentvec [(size_t)NBAGS*HH2];     // (NB,2H)
__device__ float g_bagout  [(size_t)NBAGS*OUTD];    // (NB,OUT)
__device__ float g_WwT[HH2*HH2];                    // W_word^T (N,K) K-major
__device__ float g_WsT[HH2*HH2];                    // W_sent^T

// ---------------- generic 64x64x16 fp32 NT-GEMM core ----------------
// C[m,n] = sum_k A[m*lda+k] * W[n*ldw+k]  (+bias[n])
// mode 0: store C+bias
// mode 2: partial[m*nPart+bx] = sum_{n in tile} proj[n]*tanh(C+bias)   (C not stored)
// A == nullptr -> treat A as zero. Requires M % 64 == 0, blockDim = 256.
__device__ __forceinline__ void gemm_core(
    const float* __restrict__ A, int lda,
    const float* __restrict__ W, int ldw,
    float* __restrict__ C, int ldc,
    const float* __restrict__ bias,
    const float* __restrict__ proj,
    float* __restrict__ partial, int nPart,
    int M, int N, int K, int mode)
{
    __shared__ float As[16][65];
    __shared__ float Ws[16][65];
    __shared__ float bs[64];
    __shared__ float ps[64];
    __shared__ float red[16][16];

    const int tid = threadIdx.x;
    const int tx = tid & 15;
    const int ty = tid >> 4;
    const int m0 = blockIdx.y * 64;
    const int n0 = blockIdx.x * 64;

    if (tid < 64) {
        int n = n0 + tid;
        bs[tid] = (n < N) ? bias[n] : 0.f;
        if (mode == 2) ps[tid] = (n < N) ? proj[n] : 0.f;
    }

    float acc[4][4];
#pragma unroll
    for (int i = 0; i < 4; i++)
#pragma unroll
        for (int j = 0; j < 4; j++) acc[i][j] = 0.f;

    const int ktiles = (K + 15) / 16;
    for (int kt = 0; kt < ktiles; kt++) {
        const int k0 = kt * 16;
#pragma unroll
        for (int r = 0; r < 4; r++) {
            int idx = r * 256 + tid;
            int mm = idx >> 4, kk = idx & 15;
            float v = 0.f;
            if (A) {
                int gk = k0 + kk;
                if (gk < K) v = A[(size_t)(m0 + mm) * lda + gk];
            }
            As[kk][mm] = v;
        }
#pragma unroll
        for (int r = 0; r < 4; r++) {
            int idx = r * 256 + tid;
            int nn = idx >> 4, kk = idx & 15;
            float v = 0.f;
            int gn = n0 + nn, gk = k0 + kk;
            if (gn < N && gk < K) v = W[(size_t)gn * ldw + gk];
            Ws[kk][nn] = v;
        }
        __syncthreads();
#pragma unroll
        for (int kk = 0; kk < 16; kk++) {
            float a[4], w[4];
#pragma unroll
            for (int i = 0; i < 4; i++) a[i] = As[kk][ty * 4 + i];
#pragma unroll
            for (int j = 0; j < 4; j++) w[j] = Ws[kk][tx * 4 + j];
#pragma unroll
            for (int i = 0; i < 4; i++)
#pragma unroll
                for (int j = 0; j < 4; j++)
                    acc[i][j] = fmaf(a[i], w[j], acc[i][j]);
        }
        __syncthreads();
    }

    if (mode == 2) {
        float rsum[4];
#pragma unroll
        for (int i = 0; i < 4; i++) {
            float s = 0.f;
#pragma unroll
            for (int j = 0; j < 4; j++) {
                int nn = tx * 4 + j;
                s += ps[nn] * tanhf(acc[i][j] + bs[nn]);
            }
            rsum[i] = s;
        }
#pragma unroll
        for (int i = 0; i < 4; i++) {
            red[ty][tx] = rsum[i];
            __syncthreads();
            if (tx == 0) {
                float s = 0.f;
#pragma unroll
                for (int x = 0; x < 16; x++) s += red[ty][x];
                int gm = m0 + ty * 4 + i;
                partial[(size_t)gm * nPart + blockIdx.x] = s;
            }
            __syncthreads();
        }
    } else {
#pragma unroll
        for (int i = 0; i < 4; i++) {
            int gm = m0 + ty * 4 + i;
#pragma unroll
            for (int j = 0; j < 4; j++) {
                int nn = tx * 4 + j;
                int gn = n0 + nn;
                if (gn < N) {
                    C[(size_t)gm * ldc + gn] = acc[i][j] + bs[nn];
                }
            }
        }
    }
}

// ---------------- kernel wrappers ----------------
__global__ void k_transpose(const float* __restrict__ W, int which) {
    int idx = blockIdx.x * blockDim.x + threadIdx.x;
    if (idx >= HH2 * HH2) return;
    int r = idx / HH2, c = idx - r * HH2;
    float* Wt = which ? g_WsT : g_WwT;
    Wt[c * HH2 + r] = W[idx];   // Wt[n,k] = W[k,n]
}

__global__ void k_gemm_xg(const float* __restrict__ bag,
                          const float* __restrict__ Wih,
                          const float* __restrict__ bih, int dir) {
    float* C = dir ? g_xg_r : g_xg_f;
    gemm_core(bag, IND, Wih, IND, C, G3, bih, nullptr, nullptr, 0,
              MTOK, G3, IND, 0);
}

__global__ void k_step_gemm(int i,
                            const float* __restrict__ Whhf,
                            const float* __restrict__ Whhr,
                            const float* __restrict__ bhhf,
                            const float* __restrict__ bhhr) {
    int d = blockIdx.z;
    const float* W = d ? Whhr : Whhf;
    const float* bias = d ? bhhr : bhhf;
    const float* A = nullptr;
    if (i > 0) {
        int t = d ? (TLEN - 1 - i) : i;
        int tp = d ? (t + 1) : (t - 1);
        A = g_out + ((size_t)tp * BATCH) * HH2 + d * HID;
    }
    float* C = g_hg + (size_t)d * BATCH * G3;
    gemm_core(A, HH2, W, HID, C, G3, bias, nullptr, nullptr, 0,
              BATCH, G3, HID, 0);
}

__global__ void k_gru_gate(int i) {
    int d = blockIdx.z;
    int idx = blockIdx.x * blockDim.x + threadIdx.x;
    if (idx >= BATCH * HID) return;
    int b = idx / HID, j = idx - b * HID;
    int t = d ? (TLEN - 1 - i) : i;
    const float* xg = (d ? g_xg_r : g_xg_f) + ((size_t)b * TLEN + t) * G3;
    const float* hg = g_hg + (size_t)d * BATCH * G3 + (size_t)b * G3;
    float hprev = 0.f;
    if (i > 0) {
        int tp = d ? (t + 1) : (t - 1);
        hprev = g_out[((size_t)tp * BATCH + b) * HH2 + d * HID + j];
    }
    float r = 1.f / (1.f + expf(-(xg[j] + hg[j])));
    float z = 1.f / (1.f + expf(-(xg[HID + j] + hg[HID + j])));
    float n = tanhf(xg[2 * HID + j] + r * hg[2 * HID + j]);
    float h = (1.f - z) * n + z * hprev;
    g_out[((size_t)t * BATCH + b) * HH2 + d * HID + j] = h;
}

__global__ void k_gemm_uword(const float* __restrict__ b_word,
                             const float* __restrict__ proj_word) {
    gemm_core(g_out, HH2, g_WwT, HH2, nullptr, 0, b_word, proj_word,
              g_partial, NPART, MTOK, HH2, HH2, 2);
}

__global__ void k_reduce_word() {
    int m = blockIdx.x * blockDim.x + threadIdx.x;
    if (m >= MTOK) return;
    float s = 0.f;
#pragma unroll
    for (int p = 0; p < NPART; p++) s += g_partial[(size_t)m * NPART + p];
    int t = m / BATCH, b = m - t * BATCH;
    g_scores[(size_t)b * TLEN + t] = s;   // (B,T)
}

__global__ void k_softmax_word() {
    int warp = threadIdx.x >> 5, lane = threadIdx.x & 31;
    int b = blockIdx.x * (blockDim.x >> 5) + warp;
    if (b >= BATCH) return;
    float v0 = g_scores[b * TLEN + lane];
    float v1 = g_scores[b * TLEN + lane + 32];
    float m = fmaxf(v0, v1);
#pragma unroll
    for (int o = 16; o > 0; o >>= 1) m = fmaxf(m, __shfl_xor_sync(0xffffffffu, m, o));
    float e0 = expf(v0 - m), e1 = expf(v1 - m);
    float s = e0 + e1;
#pragma unroll
    for (int o = 16; o > 0; o >>= 1) s += __shfl_xor_sync(0xffffffffu, s, o);
    float inv = 1.f / s;
    g_scores[b * TLEN + lane]      = e0 * inv;
    g_scores[b * TLEN + lane + 32] = e1 * inv;
}

__global__ void k_wordvec() {
    int idx = blockIdx.x * blockDim.x + threadIdx.x;
    if (idx >= BATCH * HH2) return;
    int b = idx / HH2, h = idx - b * HH2;
    float s = 0.f;
#pragma unroll 4
    for (int t = 0; t < TLEN; t++)
        s += g_scores[b * TLEN + t] * g_out[((size_t)t * BATCH + b) * HH2 + h];
    g_wordvec[idx] = s;
}

__global__ void k_gemm_usent(const float* __restrict__ b_sent,
                             const float* __restrict__ proj_sent) {
    gemm_core(g_wordvec, HH2, g_WsT, HH2, nullptr, 0, b_sent, proj_sent,
              g_partial2, NPART, BATCH, HH2, HH2, 2);
}

__global__ void k_reduce_sent() {
    int b = blockIdx.x * blockDim.x + threadIdx.x;
    if (b >= BATCH) return;
    float s = 0.f;
#pragma unroll
    for (int p = 0; p < NPART; p++) s += g_partial2[(size_t)b * NPART + p];
    g_scores2[b] = s;
}

__global__ void k_softmax_sent() {
    int nb = blockIdx.x * blockDim.x + threadIdx.x;
    if (nb >= NBAGS) return;
    float m = -1e30f;
#pragma unroll
    for (int s = 0; s < MSENT; s++) m = fmaxf(m, g_scores2[nb * MSENT + s]);
    float sum = 0.f;
    float e[MSENT];
#pragma unroll
    for (int s = 0; s < MSENT; s++) { e[s] = expf(g_scores2[nb * MSENT + s] - m); sum += e[s]; }
    float inv = 1.f / sum;
#pragma unroll
    for (int s = 0; s < MSENT; s++) g_scores2[nb * MSENT + s] = e[s] * inv;
}

__global__ void k_sentvec() {
    int idx = blockIdx.x * blockDim.x + threadIdx.x;
    if (idx >= NBAGS * HH2) return;
    int nb = idx / HH2, h = idx - nb * HH2;
    float s = 0.f;
#pragma unroll
    for (int ss = 0; ss < MSENT; ss++)
        s += g_scores2[nb * MSENT + ss] * g_wordvec[(size_t)(nb * MSENT + ss) * HH2 + h];
    g_sentvec[idx] = s;
}

__global__ void k_gemm_fc(const float* __restrict__ fcW,
                          const float* __restrict__ fcb) {
    gemm_core(g_sentvec, HH2, fcW, HH2, g_bagout, OUTD, fcb, nullptr, nullptr, 0,
              NBAGS, OUTD, HH2, 0);
}

__global__ void k_zero(float* __restrict__ out, int n) {
    int idx = blockIdx.x * blockDim.x + threadIdx.x;
    if (idx < n) out[idx] = 0.f;
}

__global__ void k_scatter(const int* __restrict__ pairs, float* __restrict__ out) {
    int idx = blockIdx.x * blockDim.x + threadIdx.x;
    if (idx >= NBAGS * OUTD) return;
    int b = idx / OUTD, o = idx - b * OUTD;
    int p0 = pairs[b * 3 + 0], p1 = pairs[b * 3 + 1], p2 = pairs[b * 3 + 2];
    out[((size_t)(p0 * NENT + p1) * NENT + p2) * OUTD + o] = g_bagout[idx];
}

// ---------------- launch ----------------
extern "C" void kernel_launch(void* const* d_in, const int* in_sizes, int n_in,
                              void* d_out, int out_size) {
    const float* bag       = (const float*)d_in[0];
    const float* W_ih_f    = (const float*)d_in[1];
    const float* W_hh_f    = (const float*)d_in[2];
    const float* b_ih_f    = (const float*)d_in[3];
    const float* b_hh_f    = (const float*)d_in[4];
    const float* W_ih_r    = (const float*)d_in[5];
    const float* W_hh_r    = (const float*)d_in[6];
    const float* b_ih_r    = (const float*)d_in[7];
    const float* b_hh_r    = (const float*)d_in[8];
    const float* W_word    = (const float*)d_in[9];
    const float* b_word    = (const float*)d_in[10];
    const float* proj_word = (const float*)d_in[11];
    const float* W_sent    = (const float*)d_in[12];
    const float* b_sent    = (const float*)d_in[13];
    const float* proj_sent = (const float*)d_in[14];
    const float* fc_W      = (const float*)d_in[15];
    const float* fc_b      = (const float*)d_in[16];
    const int*   pairs     = (const int*)d_in[17];
    float* out = (float*)d_out;

    // weight transposes for the NN-form attention GEMMs
    k_transpose<<<(HH2 * HH2 + 255) / 256, 256>>>(W_word, 0);
    k_transpose<<<(HH2 * HH2 + 255) / 256, 256>>>(W_sent, 1);

    // input projections (both directions)
    dim3 gxg((G3 + 63) / 64, MTOK / 64);
    k_gemm_xg<<<gxg, 256>>>(bag, W_ih_f, b_ih_f, 0);
    k_gemm_xg<<<gxg, 256>>>(bag, W_ih_r, b_ih_r, 1);

    // GRU recurrence (both directions batched in z)
    dim3 gstep((G3 + 63) / 64, BATCH / 64, 2);
    dim3 ggate((BATCH * HID + 255) / 256, 1, 2);
    for (int i = 0; i < TLEN; i++) {
        k_step_gemm<<<gstep, 256>>>(i, W_hh_f, W_hh_r, b_hh_f, b_hh_r);
        k_gru_gate<<<ggate, 256>>>(i);
    }

    // word attention
    k_gemm_uword<<<dim3(NPART, MTOK / 64), 256>>>(b_word, proj_word);
    k_reduce_word<<<(MTOK + 255) / 256, 256>>>();
    k_softmax_word<<<BATCH / 8, 256>>>();
    k_wordvec<<<(BATCH * HH2 + 255) / 256, 256>>>();

    // sentence attention
    k_gemm_usent<<<dim3(NPART, BATCH / 64), 256>>>(b_sent, proj_sent);
    k_reduce_sent<<<(BATCH + 255) / 256, 256>>>();
    k_softmax_sent<<<(NBAGS + 255) / 256, 256>>>();
    k_sentvec<<<(NBAGS * HH2 + 255) / 256, 256>>>();

    // classifier + scatter
    k_gemm_fc<<<dim3(1, NBAGS / 64), 256>>>(fc_W, fc_b);
    k_zero<<<(out_size + 255) / 256, 256>>>(out, out_size);
    k_scatter<<<(NBAGS * OUTD + 255) / 256, 256>>>(pairs, out);
}

// round 3
// speedup vs baseline: 1.6093x; 1.6093x over previous
#include <cuda_runtime.h>
#include <cuda_bf16.h>

// ---------------- problem constants ----------------
#define NBAGS 512
#define MSENT 8
#define TLEN  64
#define IND   360
#define HID   230
#define OUTD  53
#define NDOCS 32
#define NENT  8

#define BATCH (NBAGS*MSENT)   // 4096
#define G3    (3*HID)         // 690
#define HH2   (2*HID)         // 460
#define MTOK  (BATCH*TLEN)    // 262144
#define NPART 8               // ceil(460/64)

// ---------------- scratch (device globals; no allocation allowed) ----------------
__device__ __align__(256) float g_xg_f[(size_t)BATCH*TLEN*G3];
__device__ __align__(256) float g_xg_r[(size_t)BATCH*TLEN*G3];
__device__ __align__(256) float g_out [(size_t)TLEN*BATCH*HH2];
__device__ __align__(256) float g_hg  [(size_t)2*BATCH*G3];
__device__ __align__(256) float g_partial [(size_t)MTOK*NPART];
__device__ __align__(256) float g_scores  [(size_t)BATCH*TLEN];
__device__ __align__(256) float g_wordvec [(size_t)BATCH*HH2];
__device__ __align__(256) float g_partial2[(size_t)BATCH*NPART];
__device__ __align__(256) float g_scores2 [BATCH];
__device__ __align__(256) float g_sentvec [(size_t)NBAGS*HH2];
__device__ __align__(256) float g_bagout  [(size_t)NBAGS*OUTD];
__device__ __align__(256) float g_WwT[HH2*HH2];
__device__ __align__(256) float g_WsT[HH2*HH2];

// ---------------- 128x64x16 fp32 NT-GEMM core, 8x4 micro-tile ----------------
// C[m,n] = sum_k A[m*lda+k] * W[n*ldw+k]  (+bias[n])
// mode 0: store C+bias
// mode 2: partial[m*nPart+bx] = sum_{n in tile} proj[n]*tanh(C+bias)  (C not stored)
// A == nullptr -> zero. Requires M % 128 == 0, blockDim = 256.
// vecA/vecW: gmem float4 path allowed (base 16B-aligned, ld % 4 == 0).
#define BM 128
#define BN 64
#define BK 16

__device__ __forceinline__ void gemm_core(
    const float* __restrict__ A, int lda,
    const float* __restrict__ W, int ldw,
    float* __restrict__ C, int ldc,
    const float* __restrict__ bias,
    const float* __restrict__ proj,
    float* __restrict__ partial, int nPart,
    int M, int N, int K, int mode,
    bool vecA, bool vecW)
{
    __shared__ float As[BK][BM + 4];   // 132 floats/row -> 16B-aligned rows
    __shared__ float Ws[BK][BN + 4];   // 68 floats/row  -> 16B-aligned rows
    __shared__ float bs[BN];
    __shared__ float ps[BN];
    __shared__ float red[16][16];

    const int tid = threadIdx.x;
    const int tx = tid & 15;          // n: 16 x 4 = 64
    const int ty = tid >> 4;          // m: 16 x 8 = 128
    const int m0 = blockIdx.y * BM;
    const int n0 = blockIdx.x * BN;

    if (tid < BN) {
        int n = n0 + tid;
        bs[tid] = (n < N) ? bias[n] : 0.f;
        if (mode == 2) ps[tid] = (n < N) ? proj[n] : 0.f;
    }

    float acc[8][4];
#pragma unroll
    for (int i = 0; i < 8; i++)
#pragma unroll
        for (int j = 0; j < 4; j++) acc[i][j] = 0.f;

    const int ktiles = (K + BK - 1) / BK;
    for (int kt = 0; kt < ktiles; kt++) {
        const int k0 = kt * BK;

        // --- load A tile: 128 x 16 = 512 float4 groups, 2 per thread ---
#pragma unroll
        for (int r = 0; r < 2; r++) {
            int lin = r * 256 + tid;          // 0..511
            int kk4 = (lin & 3) * 4;          // k group start
            int mm  = lin >> 2;               // 0..127
            float v0 = 0.f, v1 = 0.f, v2 = 0.f, v3 = 0.f;
            if (A) {
                int gk = k0 + kk4;
                const float* ap = A + (size_t)(m0 + mm) * lda + gk;
                if (vecA && gk + 3 < K) {
                    float4 f = *reinterpret_cast<const float4*>(ap);
                    v0 = f.x; v1 = f.y; v2 = f.z; v3 = f.w;
                } else {
                    if (gk + 0 < K) v0 = ap[0];
                    if (gk + 1 < K) v1 = ap[1];
                    if (gk + 2 < K) v2 = ap[2];
                    if (gk + 3 < K) v3 = ap[3];
                }
            }
            As[kk4 + 0][mm] = v0;
            As[kk4 + 1][mm] = v1;
            As[kk4 + 2][mm] = v2;
            As[kk4 + 3][mm] = v3;
        }

        // --- load W tile: 64 x 16 = 256 float4 groups, 1 per thread ---
        {
            int lin = tid;
            int kk4 = (lin & 3) * 4;
            int nn  = lin >> 2;               // 0..63
            int gn  = n0 + nn;
            float v0 = 0.f, v1 = 0.f, v2 = 0.f, v3 = 0.f;
            if (gn < N) {
                int gk = k0 + kk4;
                const float* wp = W + (size_t)gn * ldw + gk;
                if (vecW && gk + 3 < K) {
                    float4 f = *reinterpret_cast<const float4*>(wp);
                    v0 = f.x; v1 = f.y; v2 = f.z; v3 = f.w;
                } else {
                    if (gk + 0 < K) v0 = wp[0];
                    if (gk + 1 < K) v1 = wp[1];
                    if (gk + 2 < K) v2 = wp[2];
                    if (gk + 3 < K) v3 = wp[3];
                }
            }
            Ws[kk4 + 0][nn] = v0;
            Ws[kk4 + 1][nn] = v1;
            Ws[kk4 + 2][nn] = v2;
            Ws[kk4 + 3][nn] = v3;
        }
        __syncthreads();

#pragma unroll
        for (int kk = 0; kk < BK; kk++) {
            float4 a0 = *reinterpret_cast<const float4*>(&As[kk][ty * 8]);
            float4 a1 = *reinterpret_cast<const float4*>(&As[kk][ty * 8 + 4]);
            float4 w0 = *reinterpret_cast<const float4*>(&Ws[kk][tx * 4]);
            float a[8] = {a0.x, a0.y, a0.z, a0.w, a1.x, a1.y, a1.z, a1.w};
            float w[4] = {w0.x, w0.y, w0.z, w0.w};
#pragma unroll
            for (int i = 0; i < 8; i++)
#pragma unroll
                for (int j = 0; j < 4; j++)
                    acc[i][j] = fmaf(a[i], w[j], acc[i][j]);
        }
        __syncthreads();
    }

    if (mode == 2) {
        float rsum[8];
#pragma unroll
        for (int i = 0; i < 8; i++) {
            float s = 0.f;
#pragma unroll
            for (int j = 0; j < 4; j++) {
                int nn = tx * 4 + j;
                s += ps[nn] * tanhf(acc[i][j] + bs[nn]);
            }
            rsum[i] = s;
        }
#pragma unroll
        for (int i = 0; i < 8; i++) {
            red[ty][tx] = rsum[i];
            __syncthreads();
            if (tx == 0) {
                float s = 0.f;
#pragma unroll
                for (int x = 0; x < 16; x++) s += red[ty][x];
                int gm = m0 + ty * 8 + i;
                partial[(size_t)gm * nPart + blockIdx.x] = s;
            }
            __syncthreads();
        }
    } else {
#pragma unroll
        for (int i = 0; i < 8; i++) {
            int gm = m0 + ty * 8 + i;
#pragma unroll
            for (int j = 0; j < 4; j++) {
                int nn = tx * 4 + j;
                int gn = n0 + nn;
                if (gn < N) C[(size_t)gm * ldc + gn] = acc[i][j] + bs[nn];
            }
        }
    }
}

// ---------------- kernel wrappers ----------------
__global__ void k_transpose(const float* __restrict__ W, int which) {
    int idx = blockIdx.x * blockDim.x + threadIdx.x;
    if (idx >= HH2 * HH2) return;
    int r = idx / HH2, c = idx - r * HH2;
    float* Wt = which ? g_WsT : g_WwT;
    Wt[c * HH2 + r] = W[idx];
}

__global__ void k_gemm_xg(const float* __restrict__ bag,
                          const float* __restrict__ Wih,
                          const float* __restrict__ bih, int dir) {
    float* C = dir ? g_xg_r : g_xg_f;
    gemm_core(bag, IND, Wih, IND, C, G3, bih, nullptr, nullptr, 0,
              MTOK, G3, IND, 0, true, true);
}

__global__ void k_step_gemm(int i,
                            const float* __restrict__ Whhf,
                            const float* __restrict__ Whhr,
                            const float* __restrict__ bhhf,
                            const float* __restrict__ bhhr) {
    int d = blockIdx.z;
    const float* W = d ? Whhr : Whhf;
    const float* bias = d ? bhhr : bhhf;
    const float* A = nullptr;
    if (i > 0) {
        int t = d ? (TLEN - 1 - i) : i;
        int tp = d ? (t + 1) : (t - 1);
        A = g_out + ((size_t)tp * BATCH) * HH2 + d * HID;
    }
    float* C = g_hg + (size_t)d * BATCH * G3;
    gemm_core(A, HH2, W, HID, C, G3, bias, nullptr, nullptr, 0,
              BATCH, G3, HID, 0, false, false);
}

__global__ void k_gru_gate(int i) {
    int d = blockIdx.z;
    int idx = blockIdx.x * blockDim.x + threadIdx.x;
    if (idx >= BATCH * HID) return;
    int b = idx / HID, j = idx - b * HID;
    int t = d ? (TLEN - 1 - i) : i;
    const float* xg = (d ? g_xg_r : g_xg_f) + ((size_t)b * TLEN + t) * G3;
    const float* hg = g_hg + (size_t)d * BATCH * G3 + (size_t)b * G3;
    float hprev = 0.f;
    if (i > 0) {
        int tp = d ? (t + 1) : (t - 1);
        hprev = g_out[((size_t)tp * BATCH + b) * HH2 + d * HID + j];
    }
    float r = 1.f / (1.f + expf(-(xg[j] + hg[j])));
    float z = 1.f / (1.f + expf(-(xg[HID + j] + hg[HID + j])));
    float n = tanhf(xg[2 * HID + j] + r * hg[2 * HID + j]);
    float h = (1.f - z) * n + z * hprev;
    g_out[((size_t)t * BATCH + b) * HH2 + d * HID + j] = h;
}

__global__ void k_gemm_uword(const float* __restrict__ b_word,
                             const float* __restrict__ proj_word) {
    gemm_core(g_out, HH2, g_WwT, HH2, nullptr, 0, b_word, proj_word,
              g_partial, NPART, MTOK, HH2, HH2, 2, true, true);
}

__global__ void k_reduce_word() {
    int m = blockIdx.x * blockDim.x + threadIdx.x;
    if (m >= MTOK) return;
    float s = 0.f;
#pragma unroll
    for (int p = 0; p < NPART; p++) s += g_partial[(size_t)m * NPART + p];
    int t = m / BATCH, b = m - t * BATCH;
    g_scores[(size_t)b * TLEN + t] = s;
}

__global__ void k_softmax_word() {
    int warp = threadIdx.x >> 5, lane = threadIdx.x & 31;
    int b = blockIdx.x * (blockDim.x >> 5) + warp;
    if (b >= BATCH) return;
    float v0 = g_scores[b * TLEN + lane];
    float v1 = g_scores[b * TLEN + lane + 32];
    float m = fmaxf(v0, v1);
#pragma unroll
    for (int o = 16; o > 0; o >>= 1) m = fmaxf(m, __shfl_xor_sync(0xffffffffu, m, o));
    float e0 = expf(v0 - m), e1 = expf(v1 - m);
    float s = e0 + e1;
#pragma unroll
    for (int o = 16; o > 0; o >>= 1) s += __shfl_xor_sync(0xffffffffu, s, o);
    float inv = 1.f / s;
    g_scores[b * TLEN + lane]      = e0 * inv;
    g_scores[b * TLEN + lane + 32] = e1 * inv;
}

__global__ void k_wordvec() {
    int idx = blockIdx.x * blockDim.x + threadIdx.x;
    if (idx >= BATCH * HH2) return;
    int b = idx / HH2, h = idx - b * HH2;
    float s = 0.f;
#pragma unroll 4
    for (int t = 0; t < TLEN; t++)
        s += g_scores[b * TLEN + t] * g_out[((size_t)t * BATCH + b) * HH2 + h];
    g_wordvec[idx] = s;
}

__global__ void k_gemm_usent(const float* __restrict__ b_sent,
                             const float* __restrict__ proj_sent) {
    gemm_core(g_wordvec, HH2, g_WsT, HH2, nullptr, 0, b_sent, proj_sent,
              g_partial2, NPART, BATCH, HH2, HH2, 2, true, true);
}

__global__ void k_reduce_sent() {
    int b = blockIdx.x * blockDim.x + threadIdx.x;
    if (b >= BATCH) return;
    float s = 0.f;
#pragma unroll
    for (int p = 0; p < NPART; p++) s += g_partial2[(size_t)b * NPART + p];
    g_scores2[b] = s;
}

__global__ void k_softmax_sent() {
    int nb = blockIdx.x * blockDim.x + threadIdx.x;
    if (nb >= NBAGS) return;
    float m = -1e30f;
#pragma unroll
    for (int s = 0; s < MSENT; s++) m = fmaxf(m, g_scores2[nb * MSENT + s]);
    float sum = 0.f;
    float e[MSENT];
#pragma unroll
    for (int s = 0; s < MSENT; s++) { e[s] = expf(g_scores2[nb * MSENT + s] - m); sum += e[s]; }
    float inv = 1.f / sum;
#pragma unroll
    for (int s = 0; s < MSENT; s++) g_scores2[nb * MSENT + s] = e[s] * inv;
}

__global__ void k_sentvec() {
    int idx = blockIdx.x * blockDim.x + threadIdx.x;
    if (idx >= NBAGS * HH2) return;
    int nb = idx / HH2, h = idx - nb * HH2;
    float s = 0.f;
#pragma unroll
    for (int ss = 0; ss < MSENT; ss++)
        s += g_scores2[nb * MSENT + ss] * g_wordvec[(size_t)(nb * MSENT + ss) * HH2 + h];
    g_sentvec[idx] = s;
}

__global__ void k_gemm_fc(const float* __restrict__ fcW,
                          const float* __restrict__ fcb) {
    gemm_core(g_sentvec, HH2, fcW, HH2, g_bagout, OUTD, fcb, nullptr, nullptr, 0,
              NBAGS, OUTD, HH2, 0, true, true);
}

__global__ void k_zero(float* __restrict__ out, int n) {
    int idx = blockIdx.x * blockDim.x + threadIdx.x;
    if (idx < n) out[idx] = 0.f;
}

__global__ void k_scatter(const int* __restrict__ pairs, float* __restrict__ out) {
    int idx = blockIdx.x * blockDim.x + threadIdx.x;
    if (idx >= NBAGS * OUTD) return;
    int b = idx / OUTD, o = idx - b * OUTD;
    int p0 = pairs[b * 3 + 0], p1 = pairs[b * 3 + 1], p2 = pairs[b * 3 + 2];
    out[((size_t)(p0 * NENT + p1) * NENT + p2) * OUTD + o] = g_bagout[idx];
}

// ---------------- launch ----------------
extern "C" void kernel_launch(void* const* d_in, const int* in_sizes, int n_in,
                              void* d_out, int out_size) {
    const float* bag       = (const float*)d_in[0];
    const float* W_ih_f    = (const float*)d_in[1];
    const float* W_hh_f    = (const float*)d_in[2];
    const float* b_ih_f    = (const float*)d_in[3];
    const float* b_hh_f    = (const float*)d_in[4];
    const float* W_ih_r    = (const float*)d_in[5];
    const float* W_hh_r    = (const float*)d_in[6];
    const float* b_ih_r    = (const float*)d_in[7];
    const float* b_hh_r    = (const float*)d_in[8];
    const float* W_word    = (const float*)d_in[9];
    const float* b_word    = (const float*)d_in[10];
    const float* proj_word = (const float*)d_in[11];
    const float* W_sent    = (const float*)d_in[12];
    const float* b_sent    = (const float*)d_in[13];
    const float* proj_sent = (const float*)d_in[14];
    const float* fc_W      = (const float*)d_in[15];
    const float* fc_b      = (const float*)d_in[16];
    const int*   pairs     = (const int*)d_in[17];
    float* out = (float*)d_out;

    k_transpose<<<(HH2 * HH2 + 255) / 256, 256>>>(W_word, 0);
    k_transpose<<<(HH2 * HH2 + 255) / 256, 256>>>(W_sent, 1);

    // input projections (both directions)
    dim3 gxg((G3 + BN - 1) / BN, MTOK / BM);
    k_gemm_xg<<<gxg, 256>>>(bag, W_ih_f, b_ih_f, 0);
    k_gemm_xg<<<gxg, 256>>>(bag, W_ih_r, b_ih_r, 1);

    // GRU recurrence (both directions batched in z)
    dim3 gstep((G3 + BN - 1) / BN, BATCH / BM, 2);
    dim3 ggate((BATCH * HID + 255) / 256, 1, 2);
    for (int i = 0; i < TLEN; i++) {
        k_step_gemm<<<gstep, 256>>>(i, W_hh_f, W_hh_r, b_hh_f, b_hh_r);
        k_gru_gate<<<ggate, 256>>>(i);
    }

    // word attention
    k_gemm_uword<<<dim3(NPART, MTOK / BM), 256>>>(b_word, proj_word);
    k_reduce_word<<<(MTOK + 255) / 256, 256>>>();
    k_softmax_word<<<BATCH / 8, 256>>>();
    k_wordvec<<<(BATCH * HH2 + 255) / 256, 256>>>();

    // sentence attention
    k_gemm_usent<<<dim3(NPART, BATCH / BM), 256>>>(b_sent, proj_sent);
    k_reduce_sent<<<(BATCH + 255) / 256, 256>>>();
    k_softmax_sent<<<(NBAGS + 255) / 256, 256>>>();
    k_sentvec<<<(NBAGS * HH2 + 255) / 256, 256>>>();

    // classifier + scatter
    k_gemm_fc<<<dim3(1, NBAGS / BM), 256>>>(fc_W, fc_b);
    k_zero<<<(out_size + 255) / 256, 256>>>(out, out_size);
    k_scatter<<<(NBAGS * OUTD + 255) / 256, 256>>>(pairs, out);
}

// round 4
// speedup vs baseline: 1.7580x; 1.0924x over previous
#include <cuda_runtime.h>
#include <cuda_bf16.h>

// ---------------- problem constants ----------------
#define NBAGS 512
#define MSENT 8
#define TLEN  64
#define IND   360
#define HID   230
#define OUTD  53
#define NDOCS 32
#define NENT  8

#define BATCH (NBAGS*MSENT)   // 4096
#define G3    (3*HID)         // 690
#define HH2   (2*HID)         // 460
#define MTOK  (BATCH*TLEN)    // 262144
#define NPART 8               // ceil(460/64)

// ---------------- scratch (device globals; no allocation allowed) ----------------
__device__ __align__(256) float g_xg_f[(size_t)BATCH*TLEN*G3];
__device__ __align__(256) float g_xg_r[(size_t)BATCH*TLEN*G3];
__device__ __align__(256) float g_out [(size_t)TLEN*BATCH*HH2];
__device__ __align__(256) float g_hg  [(size_t)2*BATCH*G3];
__device__ __align__(256) float g_partial [(size_t)MTOK*NPART];
__device__ __align__(256) float g_scores  [(size_t)BATCH*TLEN];
__device__ __align__(256) float g_wordvec [(size_t)BATCH*HH2];
__device__ __align__(256) float g_partial2[(size_t)BATCH*NPART];
__device__ __align__(256) float g_scores2 [BATCH];
__device__ __align__(256) float g_sentvec [(size_t)NBAGS*HH2];
__device__ __align__(256) float g_bagout  [(size_t)NBAGS*OUTD];
__device__ __align__(256) float g_WwT[HH2*HH2];
__device__ __align__(256) float g_WsT[HH2*HH2];

// ---------------- packed f32x2 helpers (sm_103a FFMA2) ----------------
typedef unsigned long long u64;

__device__ __forceinline__ u64 pk2(float lo, float hi) {
    u64 r;
    asm("mov.b64 %0, {%1, %2};" : "=l"(r) : "f"(lo), "f"(hi));
    return r;
}
__device__ __forceinline__ void fma2(u64& d, u64 a, u64 b) {
    asm("fma.rn.f32x2 %0, %1, %2, %0;" : "+l"(d) : "l"(a), "l"(b));
}
__device__ __forceinline__ float2 upk2(u64 v) {
    float2 r;
    asm("mov.b64 {%0, %1}, %2;" : "=f"(r.x), "=f"(r.y) : "l"(v));
    return r;
}

// ---------------- 128x64x16 fp32 NT-GEMM core, 8x4 micro-tile, FFMA2, 2-stage ----------------
// C[m,n] = sum_k A[m*lda+k] * W[n*ldw+k]  (+bias[n])
// mode 0: store C+bias
// mode 2: partial[m*nPart+bx] = sum_{n in tile} proj[n]*tanh(C+bias)  (C not stored)
// A == nullptr -> zero. Requires M % 128 == 0, blockDim = 256.
#define BM 128
#define BN 64
#define BK 16

__device__ __forceinline__ void gemm_core(
    const float* __restrict__ A, int lda,
    const float* __restrict__ W, int ldw,
    float* __restrict__ C, int ldc,
    const float* __restrict__ bias,
    const float* __restrict__ proj,
    float* __restrict__ partial, int nPart,
    int M, int N, int K, int mode,
    bool vecA, bool vecW)
{
    __shared__ float As[2][BK][BM + 4];   // 132 floats/row -> 16B-aligned rows
    __shared__ float Ws[2][BK][BN + 4];   // 68 floats/row
    __shared__ float bs[BN];
    __shared__ float ps[BN];
    __shared__ float red[16][16];

    const int tid = threadIdx.x;
    const int tx = tid & 15;          // n: 16 x 4 = 64
    const int ty = tid >> 4;          // m: 16 x 8 = 128
    const int m0 = blockIdx.y * BM;
    const int n0 = blockIdx.x * BN;

    // loader index precompute
    const int a_kk0 = (tid & 3) * 4;          // for lin = tid
    const int a_mm0 = tid >> 2;
    const int a_mm1 = (256 + tid) >> 2;       // for lin = 256 + tid (same kk4)
    const int w_kk  = (tid & 3) * 4;
    const int w_nn  = tid >> 2;
    const int w_gn  = n0 + w_nn;

    if (tid < BN) {
        int n = n0 + tid;
        bs[tid] = (n < N) ? bias[n] : 0.f;
        if (mode == 2) ps[tid] = (n < N) ? proj[n] : 0.f;
    }

    u64 acc2[8][2];
#pragma unroll
    for (int i = 0; i < 8; i++) { acc2[i][0] = 0ull; acc2[i][1] = 0ull; }

    const int ktiles = (K + BK - 1) / BK;

    // fetch helpers (predicated)
#define FETCH_A(vout, mm, k0v)                                                  \
    {                                                                           \
        (vout) = make_float4(0.f, 0.f, 0.f, 0.f);                               \
        if (A) {                                                                \
            int gk = (k0v) + a_kk0;                                             \
            const float* ap = A + (size_t)(m0 + (mm)) * lda + gk;               \
            if (vecA && gk + 3 < K) {                                           \
                (vout) = *reinterpret_cast<const float4*>(ap);                  \
            } else {                                                            \
                if (gk + 0 < K) (vout).x = ap[0];                               \
                if (gk + 1 < K) (vout).y = ap[1];                               \
                if (gk + 2 < K) (vout).z = ap[2];                               \
                if (gk + 3 < K) (vout).w = ap[3];                               \
            }                                                                   \
        }                                                                       \
    }
#define FETCH_W(vout, k0v)                                                      \
    {                                                                           \
        (vout) = make_float4(0.f, 0.f, 0.f, 0.f);                               \
        if (w_gn < N) {                                                         \
            int gk = (k0v) + w_kk;                                              \
            const float* wp = W + (size_t)w_gn * ldw + gk;                      \
            if (vecW && gk + 3 < K) {                                           \
                (vout) = *reinterpret_cast<const float4*>(wp);                  \
            } else {                                                            \
                if (gk + 0 < K) (vout).x = wp[0];                               \
                if (gk + 1 < K) (vout).y = wp[1];                               \
                if (gk + 2 < K) (vout).z = wp[2];                               \
                if (gk + 3 < K) (vout).w = wp[3];                               \
            }                                                                   \
        }                                                                       \
    }
#define STORE_TILE(buf, va0, va1, vw)                                           \
    {                                                                           \
        As[buf][a_kk0 + 0][a_mm0] = (va0).x;                                    \
        As[buf][a_kk0 + 1][a_mm0] = (va0).y;                                    \
        As[buf][a_kk0 + 2][a_mm0] = (va0).z;                                    \
        As[buf][a_kk0 + 3][a_mm0] = (va0).w;                                    \
        As[buf][a_kk0 + 0][a_mm1] = (va1).x;                                    \
        As[buf][a_kk0 + 1][a_mm1] = (va1).y;                                    \
        As[buf][a_kk0 + 2][a_mm1] = (va1).z;                                    \
        As[buf][a_kk0 + 3][a_mm1] = (va1).w;                                    \
        Ws[buf][w_kk + 0][w_nn] = (vw).x;                                       \
        Ws[buf][w_kk + 1][w_nn] = (vw).y;                                       \
        Ws[buf][w_kk + 2][w_nn] = (vw).z;                                       \
        Ws[buf][w_kk + 3][w_nn] = (vw).w;                                       \
    }

    // preload tile 0
    {
        float4 va0, va1, vw;
        FETCH_A(va0, a_mm0, 0);
        FETCH_A(va1, a_mm1, 0);
        FETCH_W(vw, 0);
        STORE_TILE(0, va0, va1, vw);
    }
    __syncthreads();

    for (int kt = 0; kt < ktiles; kt++) {
        const int cur = kt & 1;
        const bool has_next = (kt + 1 < ktiles);
        float4 pa0, pa1, pw;
        if (has_next) {
            const int k0n = (kt + 1) * BK;
            FETCH_A(pa0, a_mm0, k0n);
            FETCH_A(pa1, a_mm1, k0n);
            FETCH_W(pw, k0n);
        }

#pragma unroll
        for (int kk = 0; kk < BK; kk++) {
            float4 a0 = *reinterpret_cast<const float4*>(&As[cur][kk][ty * 8]);
            float4 a1 = *reinterpret_cast<const float4*>(&As[cur][kk][ty * 8 + 4]);
            float4 w  = *reinterpret_cast<const float4*>(&Ws[cur][kk][tx * 4]);
            u64 wp0 = pk2(w.x, w.y);
            u64 wp1 = pk2(w.z, w.w);
            float a[8] = {a0.x, a0.y, a0.z, a0.w, a1.x, a1.y, a1.z, a1.w};
#pragma unroll
            for (int i = 0; i < 8; i++) {
                u64 ab = pk2(a[i], a[i]);
                fma2(acc2[i][0], ab, wp0);
                fma2(acc2[i][1], ab, wp1);
            }
        }

        if (has_next) {
            STORE_TILE(cur ^ 1, pa0, pa1, pw);
        }
        __syncthreads();
    }
#undef FETCH_A
#undef FETCH_W
#undef STORE_TILE

    // unpack accumulators
    float accf[8][4];
#pragma unroll
    for (int i = 0; i < 8; i++) {
        float2 p0 = upk2(acc2[i][0]);
        float2 p1 = upk2(acc2[i][1]);
        accf[i][0] = p0.x; accf[i][1] = p0.y; accf[i][2] = p1.x; accf[i][3] = p1.y;
    }

    if (mode == 2) {
        float rsum[8];
#pragma unroll
        for (int i = 0; i < 8; i++) {
            float s = 0.f;
#pragma unroll
            for (int j = 0; j < 4; j++) {
                int nn = tx * 4 + j;
                s += ps[nn] * tanhf(accf[i][j] + bs[nn]);
            }
            rsum[i] = s;
        }
#pragma unroll
        for (int i = 0; i < 8; i++) {
            red[ty][tx] = rsum[i];
            __syncthreads();
            if (tx == 0) {
                float s = 0.f;
#pragma unroll
                for (int x = 0; x < 16; x++) s += red[ty][x];
                int gm = m0 + ty * 8 + i;
                partial[(size_t)gm * nPart + blockIdx.x] = s;
            }
            __syncthreads();
        }
    } else {
#pragma unroll
        for (int i = 0; i < 8; i++) {
            int gm = m0 + ty * 8 + i;
#pragma unroll
            for (int j = 0; j < 4; j++) {
                int nn = tx * 4 + j;
                int gn = n0 + nn;
                if (gn < N) C[(size_t)gm * ldc + gn] = accf[i][j] + bs[nn];
            }
        }
    }
}

// ---------------- kernel wrappers ----------------
__global__ void k_transpose(const float* __restrict__ W, int which) {
    int idx = blockIdx.x * blockDim.x + threadIdx.x;
    if (idx >= HH2 * HH2) return;
    int r = idx / HH2, c = idx - r * HH2;
    float* Wt = which ? g_WsT : g_WwT;
    Wt[c * HH2 + r] = W[idx];
}

__global__ void k_gemm_xg(const float* __restrict__ bag,
                          const float* __restrict__ Wih,
                          const float* __restrict__ bih, int dir) {
    float* C = dir ? g_xg_r : g_xg_f;
    gemm_core(bag, IND, Wih, IND, C, G3, bih, nullptr, nullptr, 0,
              MTOK, G3, IND, 0, true, true);
}

__global__ void k_step_gemm(int i,
                            const float* __restrict__ Whhf,
                            const float* __restrict__ Whhr,
                            const float* __restrict__ bhhf,
                            const float* __restrict__ bhhr) {
    int d = blockIdx.z;
    const float* W = d ? Whhr : Whhf;
    const float* bias = d ? bhhr : bhhf;
    const float* A = nullptr;
    if (i > 0) {
        int t = d ? (TLEN - 1 - i) : i;
        int tp = d ? (t + 1) : (t - 1);
        A = g_out + ((size_t)tp * BATCH) * HH2 + d * HID;
    }
    float* C = g_hg + (size_t)d * BATCH * G3;
    gemm_core(A, HH2, W, HID, C, G3, bias, nullptr, nullptr, 0,
              BATCH, G3, HID, 0, false, false);
}

__global__ void k_gru_gate(int i) {
    int d = blockIdx.z;
    int idx = blockIdx.x * blockDim.x + threadIdx.x;
    if (idx >= BATCH * HID) return;
    int b = idx / HID, j = idx - b * HID;
    int t = d ? (TLEN - 1 - i) : i;
    const float* xg = (d ? g_xg_r : g_xg_f) + ((size_t)b * TLEN + t) * G3;
    const float* hg = g_hg + (size_t)d * BATCH * G3 + (size_t)b * G3;
    float hprev = 0.f;
    if (i > 0) {
        int tp = d ? (t + 1) : (t - 1);
        hprev = g_out[((size_t)tp * BATCH + b) * HH2 + d * HID + j];
    }
    float r = 1.f / (1.f + expf(-(xg[j] + hg[j])));
    float z = 1.f / (1.f + expf(-(xg[HID + j] + hg[HID + j])));
    float n = tanhf(xg[2 * HID + j] + r * hg[2 * HID + j]);
    float h = (1.f - z) * n + z * hprev;
    g_out[((size_t)t * BATCH + b) * HH2 + d * HID + j] = h;
}

__global__ void k_gemm_uword(const float* __restrict__ b_word,
                             const float* __restrict__ proj_word) {
    gemm_core(g_out, HH2, g_WwT, HH2, nullptr, 0, b_word, proj_word,
              g_partial, NPART, MTOK, HH2, HH2, 2, true, true);
}

__global__ void k_reduce_word() {
    int m = blockIdx.x * blockDim.x + threadIdx.x;
    if (m >= MTOK) return;
    float s = 0.f;
#pragma unroll
    for (int p = 0; p < NPART; p++) s += g_partial[(size_t)m * NPART + p];
    int t = m / BATCH, b = m - t * BATCH;
    g_scores[(size_t)b * TLEN + t] = s;
}

__global__ void k_softmax_word() {
    int warp = threadIdx.x >> 5, lane = threadIdx.x & 31;
    int b = blockIdx.x * (blockDim.x >> 5) + warp;
    if (b >= BATCH) return;
    float v0 = g_scores[b * TLEN + lane];
    float v1 = g_scores[b * TLEN + lane + 32];
    float m = fmaxf(v0, v1);
#pragma unroll
    for (int o = 16; o > 0; o >>= 1) m = fmaxf(m, __shfl_xor_sync(0xffffffffu, m, o));
    float e0 = expf(v0 - m), e1 = expf(v1 - m);
    float s = e0 + e1;
#pragma unroll
    for (int o = 16; o > 0; o >>= 1) s += __shfl_xor_sync(0xffffffffu, s, o);
    float inv = 1.f / s;
    g_scores[b * TLEN + lane]      = e0 * inv;
    g_scores[b * TLEN + lane + 32] = e1 * inv;
}

__global__ void k_wordvec() {
    int idx = blockIdx.x * blockDim.x + threadIdx.x;
    if (idx >= BATCH * HH2) return;
    int b = idx / HH2, h = idx - b * HH2;
    float s = 0.f;
#pragma unroll 4
    for (int t = 0; t < TLEN; t++)
        s += g_scores[b * TLEN + t] * g_out[((size_t)t * BATCH + b) * HH2 + h];
    g_wordvec[idx] = s;
}

__global__ void k_gemm_usent(const float* __restrict__ b_sent,
                             const float* __restrict__ proj_sent) {
    gemm_core(g_wordvec, HH2, g_WsT, HH2, nullptr, 0, b_sent, proj_sent,
              g_partial2, NPART, BATCH, HH2, HH2, 2, true, true);
}

__global__ void k_reduce_sent() {
    int b = blockIdx.x * blockDim.x + threadIdx.x;
    if (b >= BATCH) return;
    float s = 0.f;
#pragma unroll
    for (int p = 0; p < NPART; p++) s += g_partial2[(size_t)b * NPART + p];
    g_scores2[b] = s;
}

__global__ void k_softmax_sent() {
    int nb = blockIdx.x * blockDim.x + threadIdx.x;
    if (nb >= NBAGS) return;
    float m = -1e30f;
#pragma unroll
    for (int s = 0; s < MSENT; s++) m = fmaxf(m, g_scores2[nb * MSENT + s]);
    float sum = 0.f;
    float e[MSENT];
#pragma unroll
    for (int s = 0; s < MSENT; s++) { e[s] = expf(g_scores2[nb * MSENT + s] - m); sum += e[s]; }
    float inv = 1.f / sum;
#pragma unroll
    for (int s = 0; s < MSENT; s++) g_scores2[nb * MSENT + s] = e[s] * inv;
}

__global__ void k_sentvec() {
    int idx = blockIdx.x * blockDim.x + threadIdx.x;
    if (idx >= NBAGS * HH2) return;
    int nb = idx / HH2, h = idx - nb * HH2;
    float s = 0.f;
#pragma unroll
    for (int ss = 0; ss < MSENT; ss++)
        s += g_scores2[nb * MSENT + ss] * g_wordvec[(size_t)(nb * MSENT + ss) * HH2 + h];
    g_sentvec[idx] = s;
}

__global__ void k_gemm_fc(const float* __restrict__ fcW,
                          const float* __restrict__ fcb) {
    gemm_core(g_sentvec, HH2, fcW, HH2, g_bagout, OUTD, fcb, nullptr, nullptr, 0,
              NBAGS, OUTD, HH2, 0, true, true);
}

__global__ void k_zero(float* __restrict__ out, int n) {
    int idx = blockIdx.x * blockDim.x + threadIdx.x;
    if (idx < n) out[idx] = 0.f;
}

__global__ void k_scatter(const int* __restrict__ pairs, float* __restrict__ out) {
    int idx = blockIdx.x * blockDim.x + threadIdx.x;
    if (idx >= NBAGS * OUTD) return;
    int b = idx / OUTD, o = idx - b * OUTD;
    int p0 = pairs[b * 3 + 0], p1 = pairs[b * 3 + 1], p2 = pairs[b * 3 + 2];
    out[((size_t)(p0 * NENT + p1) * NENT + p2) * OUTD + o] = g_bagout[idx];
}

// ---------------- launch ----------------
extern "C" void kernel_launch(void* const* d_in, const int* in_sizes, int n_in,
                              void* d_out, int out_size) {
    const float* bag       = (const float*)d_in[0];
    const float* W_ih_f    = (const float*)d_in[1];
    const float* W_hh_f    = (const float*)d_in[2];
    const float* b_ih_f    = (const float*)d_in[3];
    const float* b_hh_f    = (const float*)d_in[4];
    const float* W_ih_r    = (const float*)d_in[5];
    const float* W_hh_r    = (const float*)d_in[6];
    const float* b_ih_r    = (const float*)d_in[7];
    const float* b_hh_r    = (const float*)d_in[8];
    const float* W_word    = (const float*)d_in[9];
    const float* b_word    = (const float*)d_in[10];
    const float* proj_word = (const float*)d_in[11];
    const float* W_sent    = (const float*)d_in[12];
    const float* b_sent    = (const float*)d_in[13];
    const float* proj_sent = (const float*)d_in[14];
    const float* fc_W      = (const float*)d_in[15];
    const float* fc_b      = (const float*)d_in[16];
    const int*   pairs     = (const int*)d_in[17];
    float* out = (float*)d_out;

    k_transpose<<<(HH2 * HH2 + 255) / 256, 256>>>(W_word, 0);
    k_transpose<<<(HH2 * HH2 + 255) / 256, 256>>>(W_sent, 1);

    // input projections (both directions)
    dim3 gxg((G3 + BN - 1) / BN, MTOK / BM);
    k_gemm_xg<<<gxg, 256>>>(bag, W_ih_f, b_ih_f, 0);
    k_gemm_xg<<<gxg, 256>>>(bag, W_ih_r, b_ih_r, 1);

    // GRU recurrence (both directions batched in z)
    dim3 gstep((G3 + BN - 1) / BN, BATCH / BM, 2);
    dim3 ggate((BATCH * HID + 255) / 256, 1, 2);
    for (int i = 0; i < TLEN; i++) {
        k_step_gemm<<<gstep, 256>>>(i, W_hh_f, W_hh_r, b_hh_f, b_hh_r);
        k_gru_gate<<<ggate, 256>>>(i);
    }

    // word attention
    k_gemm_uword<<<dim3(NPART, MTOK / BM), 256>>>(b_word, proj_word);
    k_reduce_word<<<(MTOK + 255) / 256, 256>>>();
    k_softmax_word<<<BATCH / 8, 256>>>();
    k_wordvec<<<(BATCH * HH2 + 255) / 256, 256>>>();

    // sentence attention
    k_gemm_usent<<<dim3(NPART, BATCH / BM), 256>>>(b_sent, proj_sent);
    k_reduce_sent<<<(BATCH + 255) / 256, 256>>>();
    k_softmax_sent<<<(NBAGS + 255) / 256, 256>>>();
    k_sentvec<<<(NBAGS * HH2 + 255) / 256, 256>>>();

    // classifier + scatter
    k_gemm_fc<<<dim3(1, NBAGS / BM), 256>>>(fc_W, fc_b);
    k_zero<<<(out_size + 255) / 256, 256>>>(out, out_size);
    k_scatter<<<(NBAGS * OUTD + 255) / 256, 256>>>(pairs, out);
}

// round 6
// speedup vs baseline: 3.4390x; 1.9562x over previous
#include <cuda_runtime.h>
#include <cuda_bf16.h>
#include <stdint.h>

// ---------------- problem constants ----------------
#define NBAGS 512
#define MSENT 8
#define TLEN  64
#define IND   360
#define HID   230
#define OUTD  53
#define NDOCS 32
#define NENT  8

#define BATCH (NBAGS*MSENT)   // 4096
#define G3    (3*HID)         // 690
#define HH2   (2*HID)         // 460
#define MTOK  (BATCH*TLEN)    // 262144
#define NPART 4               // 512 / 128 n-tiles for attention GEMMs

// padded dims (K mult of 64, N mult of 128)
#define KP_IN   384
#define KP_HID  256
#define KP_HH2  512
#define NP_G3   768
#define NP_HH2  512
#define NP_OUT  128

// ---------------- fp32 scratch ----------------
__device__ __align__(256) float g_xg_f[(size_t)MTOK*G3];
__device__ __align__(256) float g_xg_r[(size_t)MTOK*G3];
__device__ __align__(256) float g_out [(size_t)TLEN*BATCH*HH2];
__device__ __align__(256) float g_hg  [(size_t)2*BATCH*G3];
__device__ __align__(256) float g_partial [(size_t)MTOK*NPART];
__device__ __align__(256) float g_scores  [(size_t)BATCH*TLEN];
__device__ __align__(256) float g_wordvec [(size_t)BATCH*HH2];
__device__ __align__(256) float g_partial2[(size_t)BATCH*NPART];
__device__ __align__(256) float g_scores2 [BATCH];
__device__ __align__(256) float g_sentvec [(size_t)NBAGS*HH2];
__device__ __align__(256) float g_bagout  [(size_t)NBAGS*OUTD];

// ---------------- bf16 hi/lo operand scratch (padded) ----------------
__device__ __align__(256) __nv_bfloat16 g_bag_hi[(size_t)MTOK*KP_IN];
__device__ __align__(256) __nv_bfloat16 g_bag_lo[(size_t)MTOK*KP_IN];
__device__ __align__(256) __nv_bfloat16 g_outb_hi[(size_t)MTOK*KP_HH2];
__device__ __align__(256) __nv_bfloat16 g_outb_lo[(size_t)MTOK*KP_HH2];
__device__ __align__(256) __nv_bfloat16 g_h_hi[(size_t)2*BATCH*KP_HID];
__device__ __align__(256) __nv_bfloat16 g_h_lo[(size_t)2*BATCH*KP_HID];
__device__ __align__(256) __nv_bfloat16 g_wv_hi[(size_t)BATCH*KP_HH2];
__device__ __align__(256) __nv_bfloat16 g_wv_lo[(size_t)BATCH*KP_HH2];
__device__ __align__(256) __nv_bfloat16 g_sv_hi[(size_t)NBAGS*KP_HH2];
__device__ __align__(256) __nv_bfloat16 g_sv_lo[(size_t)NBAGS*KP_HH2];
__device__ __align__(256) __nv_bfloat16 g_Wihf_hi[(size_t)NP_G3*KP_IN];
__device__ __align__(256) __nv_bfloat16 g_Wihf_lo[(size_t)NP_G3*KP_IN];
__device__ __align__(256) __nv_bfloat16 g_Wihr_hi[(size_t)NP_G3*KP_IN];
__device__ __align__(256) __nv_bfloat16 g_Wihr_lo[(size_t)NP_G3*KP_IN];
__device__ __align__(256) __nv_bfloat16 g_Whhf_hi[(size_t)NP_G3*KP_HID];
__device__ __align__(256) __nv_bfloat16 g_Whhf_lo[(size_t)NP_G3*KP_HID];
__device__ __align__(256) __nv_bfloat16 g_Whhr_hi[(size_t)NP_G3*KP_HID];
__device__ __align__(256) __nv_bfloat16 g_Whhr_lo[(size_t)NP_G3*KP_HID];
__device__ __align__(256) __nv_bfloat16 g_Ww_hi[(size_t)NP_HH2*KP_HH2];
__device__ __align__(256) __nv_bfloat16 g_Ww_lo[(size_t)NP_HH2*KP_HH2];
__device__ __align__(256) __nv_bfloat16 g_Ws_hi[(size_t)NP_HH2*KP_HH2];
__device__ __align__(256) __nv_bfloat16 g_Ws_lo[(size_t)NP_HH2*KP_HH2];
__device__ __align__(256) __nv_bfloat16 g_fc_hi[(size_t)NP_OUT*KP_HH2];
__device__ __align__(256) __nv_bfloat16 g_fc_lo[(size_t)NP_OUT*KP_HH2];

// ---------------- helpers ----------------
__device__ __forceinline__ uint32_t smem_to_u32(const void* p) {
    uint32_t a;
    asm("{ .reg .u64 t; cvta.to.shared.u64 t, %1; cvt.u32.u64 %0, t; }" : "=r"(a) : "l"(p));
    return a;
}
#define SWZ(b) ((b) ^ (((b) >> 3) & 0x70))

__device__ __forceinline__ void cpasync16(uint32_t dst, const void* src) {
    asm volatile("cp.async.ca.shared.global [%0], [%1], 16;" :: "r"(dst), "l"(src));
}
__device__ __forceinline__ void cpasync_waitall() {
    asm volatile("cp.async.commit_group;\n\tcp.async.wait_group 0;" ::: "memory");
}
__device__ __forceinline__ void ldsm_x4(uint32_t* r, uint32_t addr) {
    asm volatile("ldmatrix.sync.aligned.m8n8.x4.shared.b16 {%0,%1,%2,%3}, [%4];"
        : "=r"(r[0]), "=r"(r[1]), "=r"(r[2]), "=r"(r[3]) : "r"(addr));
}
__device__ __forceinline__ void mma_bf16(float* c, const uint32_t* a, const uint32_t* b) {
    asm volatile("mma.sync.aligned.m16n8k16.row.col.f32.bf16.bf16.f32 "
        "{%0,%1,%2,%3}, {%4,%5,%6,%7}, {%8,%9}, {%0,%1,%2,%3};"
        : "+f"(c[0]), "+f"(c[1]), "+f"(c[2]), "+f"(c[3])
        : "r"(a[0]), "r"(a[1]), "r"(a[2]), "r"(a[3]), "r"(b[0]), "r"(b[1]));
}

// ---------------- tensor-core GEMM core (mma.sync bf16, split hi/lo) ----------------
// D[128,128] = Ahi.Bhi^T + Ahi.Blo^T + Alo.Bhi^T over Kpad (chunks of 64)
// A: [Mrows][Kpad] bf16 (row-major), B: [Npad][Kpad] bf16 (= col-major KxN)
// mode 0: C[gm*ldc+gn] = D + bias[gn]   (gn < N)
// mode 2: partial[gm*nPart + blockIdx.x] = sum_n proj[n]*tanh(D + bias[n])
#define OFF_AHI 0
#define OFF_ALO 16384
#define OFF_BHI 32768
#define OFF_BLO 49152
#define OFF_BS  65536
#define OFF_PS  66048
#define OFF_RED 66560
#define TG_BYTES 68608
#define TG_SMEM (TG_BYTES + 1024)

__device__ __forceinline__ void tgemm_core(
    const __nv_bfloat16* __restrict__ Ahi, const __nv_bfloat16* __restrict__ Alo,
    const __nv_bfloat16* __restrict__ Bhi, const __nv_bfloat16* __restrict__ Blo,
    float* __restrict__ C, int ldc,
    const float* __restrict__ bias, const float* __restrict__ proj,
    float* __restrict__ partial, int nPart,
    int N, int Kpad, int mode)
{
    extern __shared__ char dsm[];
    uint32_t sraw = smem_to_u32(dsm);
    uint32_t sbase = (sraw + 1023) & ~1023u;
    char* sb = dsm + (sbase - sraw);

    const int tid  = threadIdx.x;
    const int lane = tid & 31;
    const int w    = tid >> 5;
    const int wm   = w >> 2;          // 0..1
    const int wn   = w & 3;           // 0..3
    const int g    = lane >> 2;       // 0..7
    const int tig  = lane & 3;        // 0..3
    const int m0   = blockIdx.y * 128;
    const int n0   = blockIdx.x * 128;

    float* bs  = (float*)(sb + OFF_BS);
    float* ps  = (float*)(sb + OFF_PS);
    float* red = (float*)(sb + OFF_RED);   // [4][128]

    if (tid < 128) {
        int n = n0 + tid;
        bs[tid] = (n < N) ? bias[n] : 0.f;
        ps[tid] = (mode == 2 && n < N) ? proj[n] : 0.f;
    }

    float acc[4][4][4];
#pragma unroll
    for (int mt = 0; mt < 4; mt++)
#pragma unroll
        for (int nt = 0; nt < 4; nt++)
#pragma unroll
            for (int e = 0; e < 4; e++) acc[mt][nt][e] = 0.f;

    // loader indices: 1024 16B segs per tile, 4 per thread
    const int l_row = tid >> 1;            // base for seg pattern below
    (void)l_row;

    // ldmatrix per-lane addresses (fixed per thread; k-step offset added later)
    const int a_row  = wm * 64 + (lane & 7) + ((lane >> 3) & 1) * 8;  // + mt*16
    const int a_bcol = ((lane >> 4) & 1) * 16;                        // + ks*32
    const int b_row  = wn * 32 + ((lane >> 4) & 1) * 8 + (lane & 7);  // + pr*16
    const int b_bcol = ((lane >> 3) & 1) * 16;                        // + ks*32

    const int nc = Kpad >> 6;
    for (int c = 0; c < nc; c++) {
        const int k0 = c * 64;
        // ---- stage chunk: A 128x64, B 128x64 (hi+lo each) via cp.async ----
#pragma unroll
        for (int i = 0; i < 4; i++) {
            int seg = i * 256 + tid;
            int row = seg >> 3, s = seg & 7;
            uint32_t sw = SWZ((uint32_t)(row * 128 + s * 16));
            size_t gA = (size_t)(m0 + row) * Kpad + k0 + s * 8;
            size_t gB = (size_t)(n0 + row) * Kpad + k0 + s * 8;
            cpasync16(sbase + OFF_AHI + sw, Ahi + gA);
            cpasync16(sbase + OFF_ALO + sw, Alo + gA);
            cpasync16(sbase + OFF_BHI + sw, Bhi + gB);
            cpasync16(sbase + OFF_BLO + sw, Blo + gB);
        }
        cpasync_waitall();
        __syncthreads();

#pragma unroll
        for (int ks = 0; ks < 4; ks++) {
            uint32_t ah[4][4], al[4][4], bh[4][2], bl[4][2];
#pragma unroll
            for (int mt = 0; mt < 4; mt++) {
                uint32_t boff = (uint32_t)((a_row + mt * 16) * 128 + ks * 32 + a_bcol);
                ldsm_x4(ah[mt], sbase + OFF_AHI + SWZ(boff));
                ldsm_x4(al[mt], sbase + OFF_ALO + SWZ(boff));
            }
#pragma unroll
            for (int pr = 0; pr < 2; pr++) {
                uint32_t boff = (uint32_t)((b_row + pr * 16) * 128 + ks * 32 + b_bcol);
                uint32_t t[4];
                ldsm_x4(t, sbase + OFF_BHI + SWZ(boff));
                bh[pr*2][0] = t[0]; bh[pr*2][1] = t[1];
                bh[pr*2+1][0] = t[2]; bh[pr*2+1][1] = t[3];
                ldsm_x4(t, sbase + OFF_BLO + SWZ(boff));
                bl[pr*2][0] = t[0]; bl[pr*2][1] = t[1];
                bl[pr*2+1][0] = t[2]; bl[pr*2+1][1] = t[3];
            }
#pragma unroll
            for (int mt = 0; mt < 4; mt++)
#pragma unroll
                for (int nt = 0; nt < 4; nt++) {
                    mma_bf16(acc[mt][nt], ah[mt], bh[nt]);
                    mma_bf16(acc[mt][nt], ah[mt], bl[nt]);
                    mma_bf16(acc[mt][nt], al[mt], bh[nt]);
                }
        }
        __syncthreads();
    }

    if (mode == 0) {
#pragma unroll
        for (int mt = 0; mt < 4; mt++)
#pragma unroll
            for (int h = 0; h < 2; h++) {
                int gm = m0 + wm * 64 + mt * 16 + h * 8 + g;
#pragma unroll
                for (int nt = 0; nt < 4; nt++)
#pragma unroll
                    for (int e = 0; e < 2; e++) {
                        int ln = wn * 32 + nt * 8 + tig * 2 + e;
                        int gn = n0 + ln;
                        if (gn < N)
                            C[(size_t)gm * ldc + gn] = acc[mt][nt][h * 2 + e] + bs[ln];
                    }
            }
    } else {
#pragma unroll
        for (int mt = 0; mt < 4; mt++)
#pragma unroll
            for (int h = 0; h < 2; h++) {
                float s = 0.f;
#pragma unroll
                for (int nt = 0; nt < 4; nt++)
#pragma unroll
                    for (int e = 0; e < 2; e++) {
                        int ln = wn * 32 + nt * 8 + tig * 2 + e;
                        s += ps[ln] * tanhf(acc[mt][nt][h * 2 + e] + bs[ln]);
                    }
                s += __shfl_xor_sync(0xffffffffu, s, 1);
                s += __shfl_xor_sync(0xffffffffu, s, 2);
                if (tig == 0)
                    red[wn * 128 + wm * 64 + mt * 16 + h * 8 + g] = s;
            }
        __syncthreads();
        if (tid < 128) {
            float t = red[tid] + red[128 + tid] + red[256 + tid] + red[384 + tid];
            partial[(size_t)(m0 + tid) * nPart + blockIdx.x] = t;
        }
    }
}

// ---------------- tensor GEMM wrappers ----------------
__global__ __launch_bounds__(256, 2) void k_tg_xg(const float* __restrict__ bih, int dir) {
    tgemm_core(g_bag_hi, g_bag_lo,
               dir ? g_Wihr_hi : g_Wihf_hi, dir ? g_Wihr_lo : g_Wihf_lo,
               dir ? g_xg_r : g_xg_f, G3, bih, nullptr, nullptr, 0,
               G3, KP_IN, 0);
}
__global__ __launch_bounds__(256, 2) void k_tg_step(const float* __restrict__ bhhf,
                                                    const float* __restrict__ bhhr) {
    int d = blockIdx.z;
    tgemm_core(g_h_hi + (size_t)d * BATCH * KP_HID, g_h_lo + (size_t)d * BATCH * KP_HID,
               d ? g_Whhr_hi : g_Whhf_hi, d ? g_Whhr_lo : g_Whhf_lo,
               g_hg + (size_t)d * BATCH * G3, G3, d ? bhhr : bhhf, nullptr, nullptr, 0,
               G3, KP_HID, 0);
}
__global__ __launch_bounds__(256, 2) void k_tg_word(const float* __restrict__ b_word,
                                                    const float* __restrict__ proj_word) {
    tgemm_core(g_outb_hi, g_outb_lo, g_Ww_hi, g_Ww_lo,
               nullptr, 0, b_word, proj_word, g_partial, NPART,
               HH2, KP_HH2, 2);
}
__global__ __launch_bounds__(256, 2) void k_tg_usent(const float* __restrict__ b_sent,
                                                     const float* __restrict__ proj_sent) {
    tgemm_core(g_wv_hi, g_wv_lo, g_Ws_hi, g_Ws_lo,
               nullptr, 0, b_sent, proj_sent, g_partial2, NPART,
               HH2, KP_HH2, 2);
}
__global__ __launch_bounds__(256, 2) void k_tg_fc(const float* __restrict__ fcb) {
    tgemm_core(g_sv_hi, g_sv_lo, g_fc_hi, g_fc_lo,
               g_bagout, OUTD, fcb, nullptr, nullptr, 0,
               OUTD, KP_HH2, 0);
}

// ---------------- hi/lo conversion kernels ----------------
__device__ __forceinline__ void conv_body(const float* __restrict__ src,
                                          __nv_bfloat16* __restrict__ hi,
                                          __nv_bfloat16* __restrict__ lo,
                                          int M, int K, int Kpad, size_t total) {
    size_t idx = (size_t)blockIdx.x * blockDim.x + threadIdx.x;
    if (idx >= total) return;
    int m = (int)(idx / Kpad), k = (int)(idx - (size_t)m * Kpad);
    float x = (m < M && k < K) ? src[(size_t)m * K + k] : 0.f;
    __nv_bfloat16 h = __float2bfloat16(x);
    hi[idx] = h;
    lo[idx] = __float2bfloat16(x - __bfloat162float(h));
}
__device__ __forceinline__ void conv_bodyT(const float* __restrict__ src,  // (K x N)
                                           __nv_bfloat16* __restrict__ hi,
                                           __nv_bfloat16* __restrict__ lo,
                                           int K, int N, int Kpad, size_t total) {
    size_t idx = (size_t)blockIdx.x * blockDim.x + threadIdx.x;
    if (idx >= total) return;
    int n = (int)(idx / Kpad), k = (int)(idx - (size_t)n * Kpad);
    float x = (n < N && k < K) ? src[(size_t)k * N + n] : 0.f;
    __nv_bfloat16 h = __float2bfloat16(x);
    hi[idx] = h;
    lo[idx] = __float2bfloat16(x - __bfloat162float(h));
}
__global__ void k_conv_bag(const float* __restrict__ s) {
    conv_body(s, g_bag_hi, g_bag_lo, MTOK, IND, KP_IN, (size_t)MTOK * KP_IN);
}
__global__ void k_conv_wihf(const float* __restrict__ s) {
    conv_body(s, g_Wihf_hi, g_Wihf_lo, G3, IND, KP_IN, (size_t)NP_G3 * KP_IN);
}
__global__ void k_conv_wihr(const float* __restrict__ s) {
    conv_body(s, g_Wihr_hi, g_Wihr_lo, G3, IND, KP_IN, (size_t)NP_G3 * KP_IN);
}
__global__ void k_conv_whhf(const float* __restrict__ s) {
    conv_body(s, g_Whhf_hi, g_Whhf_lo, G3, HID, KP_HID, (size_t)NP_G3 * KP_HID);
}
__global__ void k_conv_whhr(const float* __restrict__ s) {
    conv_body(s, g_Whhr_hi, g_Whhr_lo, G3, HID, KP_HID, (size_t)NP_G3 * KP_HID);
}
__global__ void k_conv_fcw(const float* __restrict__ s) {
    conv_body(s, g_fc_hi, g_fc_lo, OUTD, HH2, KP_HH2, (size_t)NP_OUT * KP_HH2);
}
__global__ void k_conv_ww(const float* __restrict__ s) {
    conv_bodyT(s, g_Ww_hi, g_Ww_lo, HH2, HH2, KP_HH2, (size_t)NP_HH2 * KP_HH2);
}
__global__ void k_conv_ws(const float* __restrict__ s) {
    conv_bodyT(s, g_Ws_hi, g_Ws_lo, HH2, HH2, KP_HH2, (size_t)NP_HH2 * KP_HH2);
}
__global__ void k_conv_out() {
    conv_body(g_out, g_outb_hi, g_outb_lo, MTOK, HH2, KP_HH2, (size_t)MTOK * KP_HH2);
}
__global__ void k_conv_wv() {
    conv_body(g_wordvec, g_wv_hi, g_wv_lo, BATCH, HH2, KP_HH2, (size_t)BATCH * KP_HH2);
}
__global__ void k_conv_sv() {
    conv_body(g_sentvec, g_sv_hi, g_sv_lo, NBAGS, HH2, KP_HH2, (size_t)NBAGS * KP_HH2);
}
__global__ void k_zero_h() {
    int idx = blockIdx.x * blockDim.x + threadIdx.x;
    if (idx >= 2 * BATCH * KP_HID) return;
    __nv_bfloat16 z = __float2bfloat16(0.f);
    g_h_hi[idx] = z;
    g_h_lo[idx] = z;
}

// ---------------- elementwise kernels ----------------
__global__ void k_gru_gate(int i) {
    int d = blockIdx.z;
    int idx = blockIdx.x * blockDim.x + threadIdx.x;
    if (idx >= BATCH * HID) return;
    int b = idx / HID, j = idx - b * HID;
    int t = d ? (TLEN - 1 - i) : i;
    const float* xg = (d ? g_xg_r : g_xg_f) + ((size_t)b * TLEN + t) * G3;
    const float* hg = g_hg + (size_t)d * BATCH * G3 + (size_t)b * G3;
    float hprev = 0.f;
    if (i > 0) {
        int tp = d ? (t + 1) : (t - 1);
        hprev = g_out[((size_t)tp * BATCH + b) * HH2 + d * HID + j];
    }
    float r = 1.f / (1.f + expf(-(xg[j] + hg[j])));
    float z = 1.f / (1.f + expf(-(xg[HID + j] + hg[HID + j])));
    float n = tanhf(xg[2 * HID + j] + r * hg[2 * HID + j]);
    float h = (1.f - z) * n + z * hprev;
    g_out[((size_t)t * BATCH + b) * HH2 + d * HID + j] = h;
    size_t hb = (size_t)d * BATCH * KP_HID + (size_t)b * KP_HID + j;
    __nv_bfloat16 hh = __float2bfloat16(h);
    g_h_hi[hb] = hh;
    g_h_lo[hb] = __float2bfloat16(h - __bfloat162float(hh));
}

__global__ void k_reduce_word() {
    int m = blockIdx.x * blockDim.x + threadIdx.x;
    if (m >= MTOK) return;
    float s = 0.f;
#pragma unroll
    for (int p = 0; p < NPART; p++) s += g_partial[(size_t)m * NPART + p];
    int t = m / BATCH, b = m - t * BATCH;
    g_scores[(size_t)b * TLEN + t] = s;
}

__global__ void k_softmax_word() {
    int warp = threadIdx.x >> 5, lane = threadIdx.x & 31;
    int b = blockIdx.x * (blockDim.x >> 5) + warp;
    if (b >= BATCH) return;
    float v0 = g_scores[b * TLEN + lane];
    float v1 = g_scores[b * TLEN + lane + 32];
    float m = fmaxf(v0, v1);
#pragma unroll
    for (int o = 16; o > 0; o >>= 1) m = fmaxf(m, __shfl_xor_sync(0xffffffffu, m, o));
    float e0 = expf(v0 - m), e1 = expf(v1 - m);
    float s = e0 + e1;
#pragma unroll
    for (int o = 16; o > 0; o >>= 1) s += __shfl_xor_sync(0xffffffffu, s, o);
    float inv = 1.f / s;
    g_scores[b * TLEN + lane]      = e0 * inv;
    g_scores[b * TLEN + lane + 32] = e1 * inv;
}

__global__ void k_wordvec() {
    int idx = blockIdx.x * blockDim.x + threadIdx.x;
    if (idx >= BATCH * HH2) return;
    int b = idx / HH2, h = idx - b * HH2;
    float s = 0.f;
#pragma unroll 4
    for (int t = 0; t < TLEN; t++)
        s += g_scores[b * TLEN + t] * g_out[((size_t)t * BATCH + b) * HH2 + h];
    g_wordvec[idx] = s;
}

__global__ void k_reduce_sent() {
    int b = blockIdx.x * blockDim.x + threadIdx.x;
    if (b >= BATCH) return;
    float s = 0.f;
#pragma unroll
    for (int p = 0; p < NPART; p++) s += g_partial2[(size_t)b * NPART + p];
    g_scores2[b] = s;
}

__global__ void k_softmax_sent() {
    int nb = blockIdx.x * blockDim.x + threadIdx.x;
    if (nb >= NBAGS) return;
    float m = -1e30f;
#pragma unroll
    for (int s = 0; s < MSENT; s++) m = fmaxf(m, g_scores2[nb * MSENT + s]);
    float sum = 0.f;
    float e[MSENT];
#pragma unroll
    for (int s = 0; s < MSENT; s++) { e[s] = expf(g_scores2[nb * MSENT + s] - m); sum += e[s]; }
    float inv = 1.f / sum;
#pragma unroll
    for (int s = 0; s < MSENT; s++) g_scores2[nb * MSENT + s] = e[s] * inv;
}

__global__ void k_sentvec() {
    int idx = blockIdx.x * blockDim.x + threadIdx.x;
    if (idx >= NBAGS * HH2) return;
    int nb = idx / HH2, h = idx - nb * HH2;
    float s = 0.f;
#pragma unroll
    for (int ss = 0; ss < MSENT; ss++)
        s += g_scores2[nb * MSENT + ss] * g_wordvec[(size_t)(nb * MSENT + ss) * HH2 + h];
    g_sentvec[idx] = s;
}

__global__ void k_zero(float* __restrict__ out, int n) {
    int idx = blockIdx.x * blockDim.x + threadIdx.x;
    if (idx < n) out[idx] = 0.f;
}

__global__ void k_scatter(const int* __restrict__ pairs, float* __restrict__ out) {
    int idx = blockIdx.x * blockDim.x + threadIdx.x;
    if (idx >= NBAGS * OUTD) return;
    int b = idx / OUTD, o = idx - b * OUTD;
    int p0 = pairs[b * 3 + 0], p1 = pairs[b * 3 + 1], p2 = pairs[b * 3 + 2];
    out[((size_t)(p0 * NENT + p1) * NENT + p2) * OUTD + o] = g_bagout[idx];
}

// ---------------- launch ----------------
extern "C" void kernel_launch(void* const* d_in, const int* in_sizes, int n_in,
                              void* d_out, int out_size) {
    const float* bag       = (const float*)d_in[0];
    const float* W_ih_f    = (const float*)d_in[1];
    const float* W_hh_f    = (const float*)d_in[2];
    const float* b_ih_f    = (const float*)d_in[3];
    const float* b_hh_f    = (const float*)d_in[4];
    const float* W_ih_r    = (const float*)d_in[5];
    const float* W_hh_r    = (const float*)d_in[6];
    const float* b_ih_r    = (const float*)d_in[7];
    const float* b_hh_r    = (const float*)d_in[8];
    const float* W_word    = (const float*)d_in[9];
    const float* b_word    = (const float*)d_in[10];
    const float* proj_word = (const float*)d_in[11];
    const float* W_sent    = (const float*)d_in[12];
    const float* b_sent    = (const float*)d_in[13];
    const float* proj_sent = (const float*)d_in[14];
    const float* fc_W      = (const float*)d_in[15];
    const float* fc_b      = (const float*)d_in[16];
    const int*   pairs     = (const int*)d_in[17];
    float* out = (float*)d_out;

    cudaFuncSetAttribute(k_tg_xg,    cudaFuncAttributeMaxDynamicSharedMemorySize, TG_SMEM);
    cudaFuncSetAttribute(k_tg_step,  cudaFuncAttributeMaxDynamicSharedMemorySize, TG_SMEM);
    cudaFuncSetAttribute(k_tg_word,  cudaFuncAttributeMaxDynamicSharedMemorySize, TG_SMEM);
    cudaFuncSetAttribute(k_tg_usent, cudaFuncAttributeMaxDynamicSharedMemorySize, TG_SMEM);
    cudaFuncSetAttribute(k_tg_fc,    cudaFuncAttributeMaxDynamicSharedMemorySize, TG_SMEM);

    // operand conversions (fp32 -> bf16 hi/lo, padded)
    k_conv_bag <<<(int)(((size_t)MTOK * KP_IN + 255) / 256), 256>>>(bag);
    k_conv_wihf<<<(NP_G3 * KP_IN + 255) / 256, 256>>>(W_ih_f);
    k_conv_wihr<<<(NP_G3 * KP_IN + 255) / 256, 256>>>(W_ih_r);
    k_conv_whhf<<<(NP_G3 * KP_HID + 255) / 256, 256>>>(W_hh_f);
    k_conv_whhr<<<(NP_G3 * KP_HID + 255) / 256, 256>>>(W_hh_r);
    k_conv_fcw <<<(NP_OUT * KP_HH2 + 255) / 256, 256>>>(fc_W);
    k_conv_ww  <<<(NP_HH2 * KP_HH2 + 255) / 256, 256>>>(W_word);
    k_conv_ws  <<<(NP_HH2 * KP_HH2 + 255) / 256, 256>>>(W_sent);
    k_zero_h   <<<(2 * BATCH * KP_HID + 255) / 256, 256>>>();

    // input projections (tensor)
    dim3 gxg(NP_G3 / 128, MTOK / 128);
    k_tg_xg<<<gxg, 256, TG_SMEM>>>(b_ih_f, 0);
    k_tg_xg<<<gxg, 256, TG_SMEM>>>(b_ih_r, 1);

    // GRU recurrence
    dim3 gstep(NP_G3 / 128, BATCH / 128, 2);
    dim3 ggate((BATCH * HID + 255) / 256, 1, 2);
    for (int i = 0; i < TLEN; i++) {
        k_tg_step<<<gstep, 256, TG_SMEM>>>(b_hh_f, b_hh_r);
        k_gru_gate<<<ggate, 256>>>(i);
    }

    // word attention
    k_conv_out<<<(int)(((size_t)MTOK * KP_HH2 + 255) / 256), 256>>>();
    k_tg_word<<<dim3(NP_HH2 / 128, MTOK / 128), 256, TG_SMEM>>>(b_word, proj_word);
    k_reduce_word<<<(MTOK + 255) / 256, 256>>>();
    k_softmax_word<<<BATCH / 8, 256>>>();
    k_wordvec<<<(BATCH * HH2 + 255) / 256, 256>>>();

    // sentence attention
    k_conv_wv<<<(BATCH * KP_HH2 + 255) / 256, 256>>>();
    k_tg_usent<<<dim3(NP_HH2 / 128, BATCH / 128), 256, TG_SMEM>>>(b_sent, proj_sent);
    k_reduce_sent<<<(BATCH + 255) / 256, 256>>>();
    k_softmax_sent<<<(NBAGS + 255) / 256, 256>>>();
    k_sentvec<<<(NBAGS * HH2 + 255) / 256, 256>>>();

    // classifier + scatter
    k_conv_sv<<<(NBAGS * KP_HH2 + 255) / 256, 256>>>();
    k_tg_fc<<<dim3(1, NBAGS / 128), 256, TG_SMEM>>>(fc_b);
    k_zero<<<(out_size + 255) / 256, 256>>>(out, out_size);
    k_scatter<<<(NBAGS * OUTD + 255) / 256, 256>>>(pairs, out);
}

// round 7
// speedup vs baseline: 3.4821x; 1.0125x over previous
#include <cuda_runtime.h>
#include <cuda_bf16.h>
#include <stdint.h>

// ---------------- problem constants ----------------
#define NBAGS 512
#define MSENT 8
#define TLEN  64
#define IND   360
#define HID   230
#define OUTD  53
#define NDOCS 32
#define NENT  8

#define BATCH (NBAGS*MSENT)   // 4096
#define G3    (3*HID)         // 690
#define HH2   (2*HID)         // 460
#define MTOK  (BATCH*TLEN)    // 262144
#define NPART 4

// padded dims
#define KP_IN   384
#define KP_HID  256
#define KP_HH2  512
#define NP_G3   768
#define NP_HH2  512
#define NP_OUT  128

// ---------------- fp32 scratch ----------------
__device__ __align__(256) float g_xg_f[(size_t)MTOK*G3];
__device__ __align__(256) float g_xg_r[(size_t)MTOK*G3];
__device__ __align__(256) float g_out [(size_t)TLEN*BATCH*HH2];
__device__ __align__(256) float g_hg  [(size_t)2*BATCH*G3];
__device__ __align__(256) float g_partial [(size_t)MTOK*NPART];
__device__ __align__(256) float g_scores  [(size_t)BATCH*TLEN];
__device__ __align__(256) float g_wordvec [(size_t)BATCH*HH2];
__device__ __align__(256) float g_partial2[(size_t)BATCH*NPART];
__device__ __align__(256) float g_scores2 [BATCH];
__device__ __align__(256) float g_bagout  [(size_t)NBAGS*OUTD];

// ---------------- bf16 hi/lo operand scratch (padded) ----------------
__device__ __align__(256) __nv_bfloat16 g_bag_hi[(size_t)MTOK*KP_IN];
__device__ __align__(256) __nv_bfloat16 g_bag_lo[(size_t)MTOK*KP_IN];
__device__ __align__(256) __nv_bfloat16 g_outb_hi[(size_t)MTOK*KP_HH2];
__device__ __align__(256) __nv_bfloat16 g_outb_lo[(size_t)MTOK*KP_HH2];
__device__ __align__(256) __nv_bfloat16 g_h_hi[(size_t)2*BATCH*KP_HID];
__device__ __align__(256) __nv_bfloat16 g_h_lo[(size_t)2*BATCH*KP_HID];
__device__ __align__(256) __nv_bfloat16 g_wv_hi[(size_t)BATCH*KP_HH2];
__device__ __align__(256) __nv_bfloat16 g_wv_lo[(size_t)BATCH*KP_HH2];
__device__ __align__(256) __nv_bfloat16 g_sv_hi[(size_t)NBAGS*KP_HH2];
__device__ __align__(256) __nv_bfloat16 g_sv_lo[(size_t)NBAGS*KP_HH2];
__device__ __align__(256) __nv_bfloat16 g_Wihf_hi[(size_t)NP_G3*KP_IN];
__device__ __align__(256) __nv_bfloat16 g_Wihf_lo[(size_t)NP_G3*KP_IN];
__device__ __align__(256) __nv_bfloat16 g_Wihr_hi[(size_t)NP_G3*KP_IN];
__device__ __align__(256) __nv_bfloat16 g_Wihr_lo[(size_t)NP_G3*KP_IN];
__device__ __align__(256) __nv_bfloat16 g_Whhf_hi[(size_t)NP_G3*KP_HID];
__device__ __align__(256) __nv_bfloat16 g_Whhf_lo[(size_t)NP_G3*KP_HID];
__device__ __align__(256) __nv_bfloat16 g_Whhr_hi[(size_t)NP_G3*KP_HID];
__device__ __align__(256) __nv_bfloat16 g_Whhr_lo[(size_t)NP_G3*KP_HID];
__device__ __align__(256) __nv_bfloat16 g_Ww_hi[(size_t)NP_HH2*KP_HH2];
__device__ __align__(256) __nv_bfloat16 g_Ww_lo[(size_t)NP_HH2*KP_HH2];
__device__ __align__(256) __nv_bfloat16 g_Ws_hi[(size_t)NP_HH2*KP_HH2];
__device__ __align__(256) __nv_bfloat16 g_Ws_lo[(size_t)NP_HH2*KP_HH2];
__device__ __align__(256) __nv_bfloat16 g_fc_hi[(size_t)NP_OUT*KP_HH2];
__device__ __align__(256) __nv_bfloat16 g_fc_lo[(size_t)NP_OUT*KP_HH2];

// ---------------- helpers ----------------
__device__ __forceinline__ uint32_t smem_to_u32(const void* p) {
    uint32_t a;
    asm("{ .reg .u64 t; cvta.to.shared.u64 t, %1; cvt.u32.u64 %0, t; }" : "=r"(a) : "l"(p));
    return a;
}
#define SWZ(b) ((b) ^ (((b) >> 3) & 0x70))

__device__ __forceinline__ void cpasync16(uint32_t dst, const void* src) {
    asm volatile("cp.async.ca.shared.global [%0], [%1], 16;" :: "r"(dst), "l"(src));
}
__device__ __forceinline__ void ldsm_x4(uint32_t* r, uint32_t addr) {
    asm volatile("ldmatrix.sync.aligned.m8n8.x4.shared.b16 {%0,%1,%2,%3}, [%4];"
        : "=r"(r[0]), "=r"(r[1]), "=r"(r[2]), "=r"(r[3]) : "r"(addr));
}
__device__ __forceinline__ void mma_bf16(float* c, const uint32_t* a, const uint32_t* b) {
    asm volatile("mma.sync.aligned.m16n8k16.row.col.f32.bf16.bf16.f32 "
        "{%0,%1,%2,%3}, {%4,%5,%6,%7}, {%8,%9}, {%0,%1,%2,%3};"
        : "+f"(c[0]), "+f"(c[1]), "+f"(c[2]), "+f"(c[3])
        : "r"(a[0]), "r"(a[1]), "r"(a[2]), "r"(a[3]), "r"(b[0]), "r"(b[1]));
}

// ---------------- tensor-core GEMM core (split hi/lo, optional 2-stage pipe) ----------------
#define STG_BYTES 65536
#define OFF_AHI 0
#define OFF_ALO 16384
#define OFF_BHI 32768
#define OFF_BLO 49152
#define TG_SMEM_1 (1*STG_BYTES + 3072 + 1024)
#define TG_SMEM_2 (2*STG_BYTES + 3072 + 1024)

template<int STAGES>
__device__ __forceinline__ void tgemm_core(
    const __nv_bfloat16* __restrict__ Ahi, const __nv_bfloat16* __restrict__ Alo,
    const __nv_bfloat16* __restrict__ Bhi, const __nv_bfloat16* __restrict__ Blo,
    float* __restrict__ C, int ldc,
    const float* __restrict__ bias, const float* __restrict__ proj,
    float* __restrict__ partial, int nPart,
    int N, int Kpad, int mode)
{
    extern __shared__ char dsm[];
    uint32_t sraw = smem_to_u32(dsm);
    uint32_t sbase = (sraw + 1023) & ~1023u;
    char* sb = dsm + (sbase - sraw);

    const int tid  = threadIdx.x;
    const int lane = tid & 31;
    const int w    = tid >> 5;
    const int wm   = w >> 2;
    const int wn   = w & 3;
    const int g    = lane >> 2;
    const int tig  = lane & 3;
    const int m0   = blockIdx.y * 128;
    const int n0   = blockIdx.x * 128;

    float* bs  = (float*)(sb + STAGES * STG_BYTES);
    float* ps  = (float*)(sb + STAGES * STG_BYTES + 512);
    float* red = (float*)(sb + STAGES * STG_BYTES + 1024);   // [4][128]

    if (tid < 128) {
        int n = n0 + tid;
        bs[tid] = (n < N) ? bias[n] : 0.f;
        ps[tid] = (mode == 2 && n < N) ? proj[n] : 0.f;
    }

    float acc[4][4][4];
#pragma unroll
    for (int mt = 0; mt < 4; mt++)
#pragma unroll
        for (int nt = 0; nt < 4; nt++)
#pragma unroll
            for (int e = 0; e < 4; e++) acc[mt][nt][e] = 0.f;

    const int a_row  = wm * 64 + (lane & 7) + ((lane >> 3) & 1) * 8;
    const int a_bcol = ((lane >> 4) & 1) * 16;
    const int b_row  = wn * 32 + ((lane >> 4) & 1) * 8 + (lane & 7);
    const int b_bcol = ((lane >> 3) & 1) * 16;

    const int nc = Kpad >> 6;

    auto load_chunk = [&](int c) {
        const uint32_t so = sbase + (uint32_t)(c % STAGES) * STG_BYTES;
        const int k0 = c * 64;
#pragma unroll
        for (int i = 0; i < 4; i++) {
            int seg = i * 256 + tid;
            int row = seg >> 3, s = seg & 7;
            uint32_t sw = SWZ((uint32_t)(row * 128 + s * 16));
            size_t gA = (size_t)(m0 + row) * Kpad + k0 + s * 8;
            size_t gB = (size_t)(n0 + row) * Kpad + k0 + s * 8;
            cpasync16(so + OFF_AHI + sw, Ahi + gA);
            cpasync16(so + OFF_ALO + sw, Alo + gA);
            cpasync16(so + OFF_BHI + sw, Bhi + gB);
            cpasync16(so + OFF_BLO + sw, Blo + gB);
        }
        asm volatile("cp.async.commit_group;" ::: "memory");
    };

    auto compute_chunk = [&](int c) {
        const uint32_t so = sbase + (uint32_t)(c % STAGES) * STG_BYTES;
#pragma unroll
        for (int ks = 0; ks < 4; ks++) {
            uint32_t ah[4][4], al[4][4], bh[4][2], bl[4][2];
#pragma unroll
            for (int mt = 0; mt < 4; mt++) {
                uint32_t boff = (uint32_t)((a_row + mt * 16) * 128 + ks * 32 + a_bcol);
                ldsm_x4(ah[mt], so + OFF_AHI + SWZ(boff));
                ldsm_x4(al[mt], so + OFF_ALO + SWZ(boff));
            }
#pragma unroll
            for (int pr = 0; pr < 2; pr++) {
                uint32_t boff = (uint32_t)((b_row + pr * 16) * 128 + ks * 32 + b_bcol);
                uint32_t t[4];
                ldsm_x4(t, so + OFF_BHI + SWZ(boff));
                bh[pr*2][0] = t[0]; bh[pr*2][1] = t[1];
                bh[pr*2+1][0] = t[2]; bh[pr*2+1][1] = t[3];
                ldsm_x4(t, so + OFF_BLO + SWZ(boff));
                bl[pr*2][0] = t[0]; bl[pr*2][1] = t[1];
                bl[pr*2+1][0] = t[2]; bl[pr*2+1][1] = t[3];
            }
#pragma unroll
            for (int mt = 0; mt < 4; mt++)
#pragma unroll
                for (int nt = 0; nt < 4; nt++) {
                    mma_bf16(acc[mt][nt], ah[mt], bh[nt]);
                    mma_bf16(acc[mt][nt], ah[mt], bl[nt]);
                    mma_bf16(acc[mt][nt], al[mt], bh[nt]);
                }
        }
    };

    if (STAGES == 2) {
        load_chunk(0);
        for (int c = 0; c < nc; c++) {
            if (c + 1 < nc) {
                load_chunk(c + 1);
                asm volatile("cp.async.wait_group 1;" ::: "memory");
            } else {
                asm volatile("cp.async.wait_group 0;" ::: "memory");
            }
            __syncthreads();
            compute_chunk(c);
            __syncthreads();
        }
    } else {
        for (int c = 0; c < nc; c++) {
            load_chunk(c);
            asm volatile("cp.async.wait_group 0;" ::: "memory");
            __syncthreads();
            compute_chunk(c);
            __syncthreads();
        }
    }

    if (mode == 0) {
#pragma unroll
        for (int mt = 0; mt < 4; mt++)
#pragma unroll
            for (int h = 0; h < 2; h++) {
                int gm = m0 + wm * 64 + mt * 16 + h * 8 + g;
#pragma unroll
                for (int nt = 0; nt < 4; nt++)
#pragma unroll
                    for (int e = 0; e < 2; e++) {
                        int ln = wn * 32 + nt * 8 + tig * 2 + e;
                        int gn = n0 + ln;
                        if (gn < N)
                            C[(size_t)gm * ldc + gn] = acc[mt][nt][h * 2 + e] + bs[ln];
                    }
            }
    } else {
#pragma unroll
        for (int mt = 0; mt < 4; mt++)
#pragma unroll
            for (int h = 0; h < 2; h++) {
                float s = 0.f;
#pragma unroll
                for (int nt = 0; nt < 4; nt++)
#pragma unroll
                    for (int e = 0; e < 2; e++) {
                        int ln = wn * 32 + nt * 8 + tig * 2 + e;
                        s += ps[ln] * tanhf(acc[mt][nt][h * 2 + e] + bs[ln]);
                    }
                s += __shfl_xor_sync(0xffffffffu, s, 1);
                s += __shfl_xor_sync(0xffffffffu, s, 2);
                if (tig == 0)
                    red[wn * 128 + wm * 64 + mt * 16 + h * 8 + g] = s;
            }
        __syncthreads();
        if (tid < 128) {
            float t = red[tid] + red[128 + tid] + red[256 + tid] + red[384 + tid];
            partial[(size_t)(m0 + tid) * nPart + blockIdx.x] = t;
        }
    }
}

// ---------------- tensor GEMM wrappers ----------------
__global__ __launch_bounds__(256, 1) void k_tg_xg(const float* __restrict__ bihf,
                                                  const float* __restrict__ bihr) {
    int dir = blockIdx.z;
    tgemm_core<2>(g_bag_hi, g_bag_lo,
                  dir ? g_Wihr_hi : g_Wihf_hi, dir ? g_Wihr_lo : g_Wihf_lo,
                  dir ? g_xg_r : g_xg_f, G3, dir ? bihr : bihf, nullptr, nullptr, 0,
                  G3, KP_IN, 0);
}
__global__ __launch_bounds__(256, 2) void k_tg_step(const float* __restrict__ bhhf,
                                                    const float* __restrict__ bhhr) {
    int d = blockIdx.z;
    tgemm_core<1>(g_h_hi + (size_t)d * BATCH * KP_HID, g_h_lo + (size_t)d * BATCH * KP_HID,
                  d ? g_Whhr_hi : g_Whhf_hi, d ? g_Whhr_lo : g_Whhf_lo,
                  g_hg + (size_t)d * BATCH * G3, G3, d ? bhhr : bhhf, nullptr, nullptr, 0,
                  G3, KP_HID, 0);
}
__global__ __launch_bounds__(256, 1) void k_tg_word(const float* __restrict__ b_word,
                                                    const float* __restrict__ proj_word) {
    tgemm_core<2>(g_outb_hi, g_outb_lo, g_Ww_hi, g_Ww_lo,
                  nullptr, 0, b_word, proj_word, g_partial, NPART,
                  HH2, KP_HH2, 2);
}
__global__ __launch_bounds__(256, 2) void k_tg_usent(const float* __restrict__ b_sent,
                                                     const float* __restrict__ proj_sent) {
    tgemm_core<1>(g_wv_hi, g_wv_lo, g_Ws_hi, g_Ws_lo,
                  nullptr, 0, b_sent, proj_sent, g_partial2, NPART,
                  HH2, KP_HH2, 2);
}
__global__ __launch_bounds__(256, 2) void k_tg_fc(const float* __restrict__ fcb) {
    tgemm_core<1>(g_sv_hi, g_sv_lo, g_fc_hi, g_fc_lo,
                  g_bagout, OUTD, fcb, nullptr, nullptr, 0,
                  OUTD, KP_HH2, 0);
}

// ---------------- hi/lo conversion kernels ----------------
__device__ __forceinline__ void conv_body(const float* __restrict__ src,
                                          __nv_bfloat16* __restrict__ hi,
                                          __nv_bfloat16* __restrict__ lo,
                                          int M, int K, int Kpad, size_t total) {
    size_t idx = (size_t)blockIdx.x * blockDim.x + threadIdx.x;
    if (idx >= total) return;
    int m = (int)(idx / Kpad), k = (int)(idx - (size_t)m * Kpad);
    float x = (m < M && k < K) ? src[(size_t)m * K + k] : 0.f;
    __nv_bfloat16 h = __float2bfloat16(x);
    hi[idx] = h;
    lo[idx] = __float2bfloat16(x - __bfloat162float(h));
}
__device__ __forceinline__ void conv_bodyT(const float* __restrict__ src,
                                           __nv_bfloat16* __restrict__ hi,
                                           __nv_bfloat16* __restrict__ lo,
                                           int K, int N, int Kpad, size_t total) {
    size_t idx = (size_t)blockIdx.x * blockDim.x + threadIdx.x;
    if (idx >= total) return;
    int n = (int)(idx / Kpad), k = (int)(idx - (size_t)n * Kpad);
    float x = (n < N && k < K) ? src[(size_t)k * N + n] : 0.f;
    __nv_bfloat16 h = __float2bfloat16(x);
    hi[idx] = h;
    lo[idx] = __float2bfloat16(x - __bfloat162float(h));
}
__global__ void k_conv_bag(const float* __restrict__ s) {
    conv_body(s, g_bag_hi, g_bag_lo, MTOK, IND, KP_IN, (size_t)MTOK * KP_IN);
}
__global__ void k_conv_wihf(const float* __restrict__ s) {
    conv_body(s, g_Wihf_hi, g_Wihf_lo, G3, IND, KP_IN, (size_t)NP_G3 * KP_IN);
}
__global__ void k_conv_wihr(const float* __restrict__ s) {
    conv_body(s, g_Wihr_hi, g_Wihr_lo, G3, IND, KP_IN, (size_t)NP_G3 * KP_IN);
}
__global__ void k_conv_whhf(const float* __restrict__ s) {
    conv_body(s, g_Whhf_hi, g_Whhf_lo, G3, HID, KP_HID, (size_t)NP_G3 * KP_HID);
}
__global__ void k_conv_whhr(const float* __restrict__ s) {
    conv_body(s, g_Whhr_hi, g_Whhr_lo, G3, HID, KP_HID, (size_t)NP_G3 * KP_HID);
}
__global__ void k_conv_fcw(const float* __restrict__ s) {
    conv_body(s, g_fc_hi, g_fc_lo, OUTD, HH2, KP_HH2, (size_t)NP_OUT * KP_HH2);
}
__global__ void k_conv_ww(const float* __restrict__ s) {
    conv_bodyT(s, g_Ww_hi, g_Ww_lo, HH2, HH2, KP_HH2, (size_t)NP_HH2 * KP_HH2);
}
__global__ void k_conv_ws(const float* __restrict__ s) {
    conv_bodyT(s, g_Ws_hi, g_Ws_lo, HH2, HH2, KP_HH2, (size_t)NP_HH2 * KP_HH2);
}
__global__ void k_zero_h() {
    int idx = blockIdx.x * blockDim.x + threadIdx.x;
    if (idx >= 2 * BATCH * KP_HID) return;
    __nv_bfloat16 z = __float2bfloat16(0.f);
    g_h_hi[idx] = z;
    g_h_lo[idx] = z;
}
// zero the pad columns [HH2, KP_HH2) of outb once
__global__ void k_zero_outb_pad() {
    size_t idx = (size_t)blockIdx.x * blockDim.x + threadIdx.x;
    size_t total = (size_t)MTOK * (KP_HH2 - HH2);
    if (idx >= total) return;
    int row = (int)(idx / (KP_HH2 - HH2));
    int col = HH2 + (int)(idx % (KP_HH2 - HH2));
    size_t o = (size_t)row * KP_HH2 + col;
    __nv_bfloat16 z = __float2bfloat16(0.f);
    g_outb_hi[o] = z;
    g_outb_lo[o] = z;
}

// ---------------- elementwise kernels ----------------
__global__ void k_gru_gate(int i) {
    int d = blockIdx.z;
    int idx = blockIdx.x * blockDim.x + threadIdx.x;
    if (idx >= BATCH * HID) return;
    int b = idx / HID, j = idx - b * HID;
    int t = d ? (TLEN - 1 - i) : i;
    const float* xg = (d ? g_xg_r : g_xg_f) + ((size_t)b * TLEN + t) * G3;
    const float* hg = g_hg + (size_t)d * BATCH * G3 + (size_t)b * G3;
    float hprev = 0.f;
    if (i > 0) {
        int tp = d ? (t + 1) : (t - 1);
        hprev = g_out[((size_t)tp * BATCH + b) * HH2 + d * HID + j];
    }
    float r = 1.f / (1.f + expf(-(xg[j] + hg[j])));
    float z = 1.f / (1.f + expf(-(xg[HID + j] + hg[HID + j])));
    float n = tanhf(xg[2 * HID + j] + r * hg[2 * HID + j]);
    float h = (1.f - z) * n + z * hprev;
    g_out[((size_t)t * BATCH + b) * HH2 + d * HID + j] = h;
    __nv_bfloat16 hh = __float2bfloat16(h);
    __nv_bfloat16 hl = __float2bfloat16(h - __bfloat162float(hh));
    // operand for next recurrence step
    size_t hb = (size_t)d * BATCH * KP_HID + (size_t)b * KP_HID + j;
    g_h_hi[hb] = hh;
    g_h_lo[hb] = hl;
    // operand for word-attention GEMM (fused conv_out)
    size_t ob = (size_t)((size_t)t * BATCH + b) * KP_HH2 + d * HID + j;
    g_outb_hi[ob] = hh;
    g_outb_lo[ob] = hl;
}

__global__ void k_reduce_word() {
    int m = blockIdx.x * blockDim.x + threadIdx.x;
    if (m >= MTOK) return;
    float s = 0.f;
#pragma unroll
    for (int p = 0; p < NPART; p++) s += g_partial[(size_t)m * NPART + p];
    int t = m / BATCH, b = m - t * BATCH;
    g_scores[(size_t)b * TLEN + t] = s;
}

__global__ void k_softmax_word() {
    int warp = threadIdx.x >> 5, lane = threadIdx.x & 31;
    int b = blockIdx.x * (blockDim.x >> 5) + warp;
    if (b >= BATCH) return;
    float v0 = g_scores[b * TLEN + lane];
    float v1 = g_scores[b * TLEN + lane + 32];
    float m = fmaxf(v0, v1);
#pragma unroll
    for (int o = 16; o > 0; o >>= 1) m = fmaxf(m, __shfl_xor_sync(0xffffffffu, m, o));
    float e0 = expf(v0 - m), e1 = expf(v1 - m);
    float s = e0 + e1;
#pragma unroll
    for (int o = 16; o > 0; o >>= 1) s += __shfl_xor_sync(0xffffffffu, s, o);
    float inv = 1.f / s;
    g_scores[b * TLEN + lane]      = e0 * inv;
    g_scores[b * TLEN + lane + 32] = e1 * inv;
}

__global__ void k_wordvec() {
    size_t idx = (size_t)blockIdx.x * blockDim.x + threadIdx.x;
    if (idx >= (size_t)BATCH * KP_HH2) return;
    int b = (int)(idx / KP_HH2), h = (int)(idx - (size_t)b * KP_HH2);
    float s = 0.f;
    if (h < HH2) {
#pragma unroll 4
        for (int t = 0; t < TLEN; t++)
            s += g_scores[b * TLEN + t] * g_out[((size_t)t * BATCH + b) * HH2 + h];
        g_wordvec[(size_t)b * HH2 + h] = s;
    }
    __nv_bfloat16 sh = __float2bfloat16(s);
    g_wv_hi[idx] = sh;
    g_wv_lo[idx] = __float2bfloat16(s - __bfloat162float(sh));
}

__global__ void k_reduce_sent() {
    int b = blockIdx.x * blockDim.x + threadIdx.x;
    if (b >= BATCH) return;
    float s = 0.f;
#pragma unroll
    for (int p = 0; p < NPART; p++) s += g_partial2[(size_t)b * NPART + p];
    g_scores2[b] = s;
}

__global__ void k_softmax_sent() {
    int nb = blockIdx.x * blockDim.x + threadIdx.x;
    if (nb >= NBAGS) return;
    float m = -1e30f;
#pragma unroll
    for (int s = 0; s < MSENT; s++) m = fmaxf(m, g_scores2[nb * MSENT + s]);
    float sum = 0.f;
    float e[MSENT];
#pragma unroll
    for (int s = 0; s < MSENT; s++) { e[s] = expf(g_scores2[nb * MSENT + s] - m); sum += e[s]; }
    float inv = 1.f / sum;
#pragma unroll
    for (int s = 0; s < MSENT; s++) g_scores2[nb * MSENT + s] = e[s] * inv;
}

__global__ void k_sentvec() {
    size_t idx = (size_t)blockIdx.x * blockDim.x + threadIdx.x;
    if (idx >= (size_t)NBAGS * KP_HH2) return;
    int nb = (int)(idx / KP_HH2), h = (int)(idx - (size_t)nb * KP_HH2);
    float s = 0.f;
    if (h < HH2) {
#pragma unroll
        for (int ss = 0; ss < MSENT; ss++)
            s += g_scores2[nb * MSENT + ss] * g_wordvec[(size_t)(nb * MSENT + ss) * HH2 + h];
    }
    __nv_bfloat16 sh = __float2bfloat16(s);
    g_sv_hi[idx] = sh;
    g_sv_lo[idx] = __float2bfloat16(s - __bfloat162float(sh));
}

__global__ void k_zero(float* __restrict__ out, int n) {
    int idx = blockIdx.x * blockDim.x + threadIdx.x;
    if (idx < n) out[idx] = 0.f;
}

__global__ void k_scatter(const int* __restrict__ pairs, float* __restrict__ out) {
    int idx = blockIdx.x * blockDim.x + threadIdx.x;
    if (idx >= NBAGS * OUTD) return;
    int b = idx / OUTD, o = idx - b * OUTD;
    int p0 = pairs[b * 3 + 0], p1 = pairs[b * 3 + 1], p2 = pairs[b * 3 + 2];
    out[((size_t)(p0 * NENT + p1) * NENT + p2) * OUTD + o] = g_bagout[idx];
}

// ---------------- launch ----------------
extern "C" void kernel_launch(void* const* d_in, const int* in_sizes, int n_in,
                              void* d_out, int out_size) {
    const float* bag       = (const float*)d_in[0];
    const float* W_ih_f    = (const float*)d_in[1];
    const float* W_hh_f    = (const float*)d_in[2];
    const float* b_ih_f    = (const float*)d_in[3];
    const float* b_hh_f    = (const float*)d_in[4];
    const float* W_ih_r    = (const float*)d_in[5];
    const float* W_hh_r    = (const float*)d_in[6];
    const float* b_ih_r    = (const float*)d_in[7];
    const float* b_hh_r    = (const float*)d_in[8];
    const float* W_word    = (const float*)d_in[9];
    const float* b_word    = (const float*)d_in[10];
    const float* proj_word = (const float*)d_in[11];
    const float* W_sent    = (const float*)d_in[12];
    const float* b_sent    = (const float*)d_in[13];
    const float* proj_sent = (const float*)d_in[14];
    const float* fc_W      = (const float*)d_in[15];
    const float* fc_b      = (const float*)d_in[16];
    const int*   pairs     = (const int*)d_in[17];
    float* out = (float*)d_out;

    cudaFuncSetAttribute(k_tg_xg,    cudaFuncAttributeMaxDynamicSharedMemorySize, TG_SMEM_2);
    cudaFuncSetAttribute(k_tg_word,  cudaFuncAttributeMaxDynamicSharedMemorySize, TG_SMEM_2);
    cudaFuncSetAttribute(k_tg_step,  cudaFuncAttributeMaxDynamicSharedMemorySize, TG_SMEM_1);
    cudaFuncSetAttribute(k_tg_usent, cudaFuncAttributeMaxDynamicSharedMemorySize, TG_SMEM_1);
    cudaFuncSetAttribute(k_tg_fc,    cudaFuncAttributeMaxDynamicSharedMemorySize, TG_SMEM_1);

    // operand conversions
    k_conv_bag <<<(int)(((size_t)MTOK * KP_IN + 255) / 256), 256>>>(bag);
    k_conv_wihf<<<(NP_G3 * KP_IN + 255) / 256, 256>>>(W_ih_f);
    k_conv_wihr<<<(NP_G3 * KP_IN + 255) / 256, 256>>>(W_ih_r);
    k_conv_whhf<<<(NP_G3 * KP_HID + 255) / 256, 256>>>(W_hh_f);
    k_conv_whhr<<<(NP_G3 * KP_HID + 255) / 256, 256>>>(W_hh_r);
    k_conv_fcw <<<(NP_OUT * KP_HH2 + 255) / 256, 256>>>(fc_W);
    k_conv_ww  <<<(NP_HH2 * KP_HH2 + 255) / 256, 256>>>(W_word);
    k_conv_ws  <<<(NP_HH2 * KP_HH2 + 255) / 256, 256>>>(W_sent);
    k_zero_h   <<<(2 * BATCH * KP_HID + 255) / 256, 256>>>();
    k_zero_outb_pad<<<(int)(((size_t)MTOK * (KP_HH2 - HH2) + 255) / 256), 256>>>();

    // input projections (both dirs in z), pipelined
    k_tg_xg<<<dim3(NP_G3 / 128, MTOK / 128, 2), 256, TG_SMEM_2>>>(b_ih_f, b_ih_r);

    // GRU recurrence
    dim3 gstep(NP_G3 / 128, BATCH / 128, 2);
    dim3 ggate((BATCH * HID + 255) / 256, 1, 2);
    for (int i = 0; i < TLEN; i++) {
        k_tg_step<<<gstep, 256, TG_SMEM_1>>>(b_hh_f, b_hh_r);
        k_gru_gate<<<ggate, 256>>>(i);
    }

    // word attention (pipelined GEMM)
    k_tg_word<<<dim3(NP_HH2 / 128, MTOK / 128), 256, TG_SMEM_2>>>(b_word, proj_word);
    k_reduce_word<<<(MTOK + 255) / 256, 256>>>();
    k_softmax_word<<<BATCH / 8, 256>>>();
    k_wordvec<<<(int)(((size_t)BATCH * KP_HH2 + 255) / 256), 256>>>();

    // sentence attention
    k_tg_usent<<<dim3(NP_HH2 / 128, BATCH / 128), 256, TG_SMEM_1>>>(b_sent, proj_sent);
    k_reduce_sent<<<(BATCH + 255) / 256, 256>>>();
    k_softmax_sent<<<(NBAGS + 255) / 256, 256>>>();
    k_sentvec<<<(int)(((size_t)NBAGS * KP_HH2 + 255) / 256), 256>>>();

    // classifier + scatter
    k_tg_fc<<<dim3(1, NBAGS / 128), 256, TG_SMEM_1>>>(fc_b);
    k_zero<<<(out_size + 255) / 256, 256>>>(out, out_size);
    k_scatter<<<(NBAGS * OUTD + 255) / 256, 256>>>(pairs, out);
}